// round 10
// baseline (speedup 1.0000x reference)
#include <cuda_runtime.h>
#include <cuda_bf16.h>
#include <cstdint>

// ---------------------------------------------------------------------------
// MistralQuantizedMLP via bf16 hi/lo split GEMMs on legacy HMMA
// (mma.sync.m16n8k16.bf16) — only fast tensor path from compute_103 PTX.
//
// R10: gu CTA 64x128pair (7168 CTAs -> tail 145us -> ~53us); down split-K
// accumulates via RED.ADD into zeroed out (k_add + partial buffers deleted);
// ILP-4 weight conversion.
// ---------------------------------------------------------------------------

static constexpr int MDIM = 4096, HDIM = 4096, IDIM = 14336;
static constexpr int THREADS = 256;
static constexpr int PITCH = 144;               // 128B row + 16B pad

// ---- down-GEMM geometry: CTA 128x256, warp 64x64, split-K=2 ----
static constexpr int BM = 128, BN = 256, BK = 64;
static constexpr int MAT_A = BM * PITCH;            // 18432
static constexpr int MAT_B = BN * PITCH;            // 36864
static constexpr int STAGE_B = 2 * MAT_A + MAT_B;   // 73728
static constexpr int STAGES = 3;
static constexpr int SMEM_B = STAGES * STAGE_B;     // 221184

// ---- fused gate/up geometry: CTA 64x(128 pair), warp 32x(32 pair) ----
static constexpr int MAT_A2 = 64 * PITCH;           // 9216
static constexpr int MAT_B2 = 128 * PITCH;          // 18432
static constexpr int STAGE2 = 2 * MAT_A2 + 2 * MAT_B2;  // 55296
static constexpr int SMEM2 = STAGES * STAGE2;           // 165888

// ---- static device scratch (allocation-free rule) ----
__device__ __align__(1024) __nv_bfloat16 g_wg[(size_t)IDIM * HDIM];
__device__ __align__(1024) __nv_bfloat16 g_wu[(size_t)IDIM * HDIM];
__device__ __align__(1024) __nv_bfloat16 g_wd[(size_t)HDIM * IDIM];
__device__ __align__(1024) __nv_bfloat16 g_xhi[(size_t)MDIM * HDIM];
__device__ __align__(1024) __nv_bfloat16 g_xlo[(size_t)MDIM * HDIM];
__device__ __align__(1024) __nv_bfloat16 g_hhi[(size_t)MDIM * IDIM];
__device__ __align__(1024) __nv_bfloat16 g_hlo[(size_t)MDIM * IDIM];

// ---------------------------------------------------------------------------
// PTX helpers
// ---------------------------------------------------------------------------
__device__ __forceinline__ void cp_async16(void* sdst, const void* gsrc) {
    uint32_t s = (uint32_t)__cvta_generic_to_shared(sdst);
    asm volatile("cp.async.cg.shared.global [%0], [%1], 16;" :: "r"(s), "l"(gsrc));
}
__device__ __forceinline__ void ldm_x4(uint32_t* a, uint32_t addr) {
    asm volatile("ldmatrix.sync.aligned.m8n8.x4.shared.b16 {%0,%1,%2,%3}, [%4];"
                 : "=r"(a[0]), "=r"(a[1]), "=r"(a[2]), "=r"(a[3]) : "r"(addr));
}
__device__ __forceinline__ void mma16816(float* c, const uint32_t* a, const uint32_t* b) {
    asm volatile("mma.sync.aligned.m16n8k16.row.col.f32.bf16.bf16.f32 "
                 "{%0,%1,%2,%3}, {%4,%5,%6,%7}, {%8,%9}, {%0,%1,%2,%3};"
                 : "+f"(c[0]), "+f"(c[1]), "+f"(c[2]), "+f"(c[3])
                 : "r"(a[0]), "r"(a[1]), "r"(a[2]), "r"(a[3]), "r"(b[0]), "r"(b[1]));
}
__device__ __forceinline__ void split1(float v, __nv_bfloat16& h, __nv_bfloat16& l) {
    h = __float2bfloat16_rn(v);
    l = __float2bfloat16_rn(v - __bfloat162float(h));
}
__device__ __forceinline__ float silu_f(float g) { return g / (1.0f + expf(-g)); }

// ---------------------------------------------------------------------------
// Fused gate+up GEMM + SwiGLU + hi/lo split epilogue.
// CTA: M=64, N=128 (both matrices). Warp: 32 x 32 pair. 8 warps (2m x 4n).
// ---------------------------------------------------------------------------
__global__ __launch_bounds__(THREADS, 1)
void k_gemm_gu(const __nv_bfloat16* __restrict__ Ahi,
               const __nv_bfloat16* __restrict__ Alo,
               const __nv_bfloat16* __restrict__ Bg,
               const __nv_bfloat16* __restrict__ Bu,
               const float* __restrict__ gs, const float* __restrict__ us,
               __nv_bfloat16* __restrict__ Hhi, __nv_bfloat16* __restrict__ Hlo,
               int K) {
    extern __shared__ __align__(128) int8_t sm[];
    const int tid = threadIdx.x, lane = tid & 31, wid = tid >> 5;
    const int wm = wid >> 2, wn = wid & 3;       // 2 x 4 -> warp tile 32 x 32(pair)
    const size_t bm = (size_t)blockIdx.x * 64;
    const size_t bn = (size_t)blockIdx.y * 128;

    const __nv_bfloat16* gA0 = Ahi + bm * K;
    const __nv_bfloat16* gA1 = Alo + bm * K;
    const __nv_bfloat16* gBg = Bg + bn * K;
    const __nv_bfloat16* gBu = Bu + bn * K;

    float accg[2][4][4], accu[2][4][4];
    #pragma unroll
    for (int i = 0; i < 2; i++)
        #pragma unroll
        for (int j = 0; j < 4; j++)
            #pragma unroll
            for (int r = 0; r < 4; r++) { accg[i][j][r] = 0.f; accu[i][j][r] = 0.f; }

    // per stage: A0 512, A1 512, Bg 1024, Bu 1024 chunks of 16B
    auto load_stage = [&](int s, int k0) {
        int8_t* base = sm + s * STAGE2;
        #pragma unroll
        for (int i = 0; i < 2; i++) {
            int c = tid + i * THREADS, row = c >> 3, ch = c & 7;
            cp_async16(base + row * PITCH + ch * 16, gA0 + (size_t)row * K + k0 + ch * 8);
        }
        #pragma unroll
        for (int i = 0; i < 2; i++) {
            int c = tid + i * THREADS, row = c >> 3, ch = c & 7;
            cp_async16(base + MAT_A2 + row * PITCH + ch * 16,
                       gA1 + (size_t)row * K + k0 + ch * 8);
        }
        #pragma unroll
        for (int i = 0; i < 4; i++) {
            int c = tid + i * THREADS, row = c >> 3, ch = c & 7;
            cp_async16(base + 2 * MAT_A2 + row * PITCH + ch * 16,
                       gBg + (size_t)row * K + k0 + ch * 8);
        }
        #pragma unroll
        for (int i = 0; i < 4; i++) {
            int c = tid + i * THREADS, row = c >> 3, ch = c & 7;
            cp_async16(base + 2 * MAT_A2 + MAT_B2 + row * PITCH + ch * 16,
                       gBu + (size_t)row * K + k0 + ch * 8);
        }
        asm volatile("cp.async.commit_group;" ::: "memory");
    };

    const int KT = K / BK;
    load_stage(0, 0);
    load_stage(1, BK);

    const uint32_t smb = (uint32_t)__cvta_generic_to_shared(sm);
    const uint32_t a_off = (uint32_t)((lane & 15) * PITCH + (lane >> 4) * 16);
    const uint32_t b_off = (uint32_t)((lane & 7) * PITCH +
                                      ((lane >> 3) & 1) * 16 +
                                      (lane >> 4) * 8 * PITCH);

    int stage = 0;
    for (int kt = 0; kt < KT; kt++) {
        asm volatile("cp.async.wait_group 1;" ::: "memory");
        __syncthreads();
        if (kt + 2 < KT) {
            int s2 = stage + 2; if (s2 >= STAGES) s2 -= STAGES;
            load_stage(s2, (kt + 2) * BK);
        } else {
            asm volatile("cp.async.commit_group;" ::: "memory");
        }

        const uint32_t st  = smb + (uint32_t)(stage * STAGE2);
        const uint32_t sA0 = st + (uint32_t)((wm * 32) * PITCH);
        const uint32_t sA1 = sA0 + (uint32_t)MAT_A2;
        const uint32_t sBg = st + 2u * MAT_A2 + (uint32_t)((wn * 32) * PITCH);
        const uint32_t sBu = sBg + (uint32_t)MAT_B2;

        #pragma unroll
        for (int ks = 0; ks < 4; ks++) {
            const uint32_t kb = (uint32_t)(ks * 32);
            uint32_t bg[4][2], bu[4][2];
            #pragma unroll
            for (int np = 0; np < 2; np++) {
                uint32_t t4[4];
                ldm_x4(t4, sBg + (uint32_t)(np * 16 * PITCH) + b_off + kb);
                bg[2*np][0] = t4[0]; bg[2*np][1] = t4[1];
                bg[2*np+1][0] = t4[2]; bg[2*np+1][1] = t4[3];
                ldm_x4(t4, sBu + (uint32_t)(np * 16 * PITCH) + b_off + kb);
                bu[2*np][0] = t4[0]; bu[2*np][1] = t4[1];
                bu[2*np+1][0] = t4[2]; bu[2*np+1][1] = t4[3];
            }
            uint32_t af[2][4];
            #pragma unroll
            for (int mi = 0; mi < 2; mi++)
                ldm_x4(af[mi], sA0 + (uint32_t)(mi * 16 * PITCH) + a_off + kb);
            #pragma unroll
            for (int mi = 0; mi < 2; mi++)
                #pragma unroll
                for (int ni = 0; ni < 4; ni++) {
                    mma16816(accg[mi][ni], af[mi], bg[ni]);
                    mma16816(accu[mi][ni], af[mi], bu[ni]);
                }
            #pragma unroll
            for (int mi = 0; mi < 2; mi++)
                ldm_x4(af[mi], sA1 + (uint32_t)(mi * 16 * PITCH) + a_off + kb);
            #pragma unroll
            for (int mi = 0; mi < 2; mi++)
                #pragma unroll
                for (int ni = 0; ni < 4; ni++) {
                    mma16816(accg[mi][ni], af[mi], bg[ni]);
                    mma16816(accu[mi][ni], af[mi], bu[ni]);
                }
        }
        if (++stage == STAGES) stage = 0;
    }

    // epilogue: scales -> SwiGLU -> hi/lo bf16 split -> store
    const int r0b = (int)bm + wm * 32;
    const int c0b = (int)bn + wn * 32;
    #pragma unroll
    for (int mi = 0; mi < 2; mi++) {
        const int r0 = r0b + mi * 16 + (lane >> 2);
        #pragma unroll
        for (int ni = 0; ni < 4; ni++) {
            const int c0 = c0b + ni * 8 + (lane & 3) * 2;
            const float gs0 = __ldg(gs + c0), gs1 = __ldg(gs + c0 + 1);
            const float us0 = __ldg(us + c0), us1 = __ldg(us + c0 + 1);
            float h00 = silu_f(accg[mi][ni][0] * gs0) * (accu[mi][ni][0] * us0);
            float h01 = silu_f(accg[mi][ni][1] * gs1) * (accu[mi][ni][1] * us1);
            float h10 = silu_f(accg[mi][ni][2] * gs0) * (accu[mi][ni][2] * us0);
            float h11 = silu_f(accg[mi][ni][3] * gs1) * (accu[mi][ni][3] * us1);
            __nv_bfloat16 a0, b0, a1, b1, a2, b2, a3, b3;
            split1(h00, a0, b0); split1(h01, a1, b1);
            split1(h10, a2, b2); split1(h11, a3, b3);
            *reinterpret_cast<__nv_bfloat162*>(Hhi + (size_t)r0 * IDIM + c0) =
                __halves2bfloat162(a0, a1);
            *reinterpret_cast<__nv_bfloat162*>(Hlo + (size_t)r0 * IDIM + c0) =
                __halves2bfloat162(b0, b1);
            *reinterpret_cast<__nv_bfloat162*>(Hhi + (size_t)(r0 + 8) * IDIM + c0) =
                __halves2bfloat162(a2, a3);
            *reinterpret_cast<__nv_bfloat162*>(Hlo + (size_t)(r0 + 8) * IDIM + c0) =
                __halves2bfloat162(b2, b3);
        }
    }
}

// ---------------------------------------------------------------------------
// Down GEMM, split-K=2: both halves RED.ADD into pre-zeroed out.
// Deterministic: exactly two commutative fp32 addends per element.
// ---------------------------------------------------------------------------
__global__ __launch_bounds__(THREADS, 1)
void k_gemm_sk(const __nv_bfloat16* __restrict__ Ahi,
               const __nv_bfloat16* __restrict__ Alo,
               const __nv_bfloat16* __restrict__ Bw,
               const float* __restrict__ scale,
               float* __restrict__ C, int N, int Kld, int Kloc) {
    extern __shared__ __align__(128) int8_t sm[];
    const int tid = threadIdx.x, lane = tid & 31, wid = tid >> 5;
    const int wm = wid >> 2, wn = wid & 3;
    const size_t bm = (size_t)blockIdx.x * BM;
    const size_t bn = (size_t)blockIdx.y * BN;
    const int k0g = blockIdx.z * Kloc;

    const __nv_bfloat16* gA0 = Ahi + bm * Kld + k0g;
    const __nv_bfloat16* gA1 = Alo + bm * Kld + k0g;
    const __nv_bfloat16* gB  = Bw  + bn * Kld + k0g;

    float acc[4][8][4];
    #pragma unroll
    for (int i = 0; i < 4; i++)
        #pragma unroll
        for (int j = 0; j < 8; j++)
            #pragma unroll
            for (int r = 0; r < 4; r++) acc[i][j][r] = 0.0f;

    auto load_stage = [&](int s, int k0) {
        int8_t* base = sm + s * STAGE_B;
        #pragma unroll
        for (int i = 0; i < 4; i++) {
            int c = tid + i * THREADS, row = c >> 3, ch = c & 7;
            cp_async16(base + row * PITCH + ch * 16,
                       gA0 + (size_t)row * Kld + k0 + ch * 8);
        }
        #pragma unroll
        for (int i = 0; i < 4; i++) {
            int c = tid + i * THREADS, row = c >> 3, ch = c & 7;
            cp_async16(base + MAT_A + row * PITCH + ch * 16,
                       gA1 + (size_t)row * Kld + k0 + ch * 8);
        }
        #pragma unroll
        for (int i = 0; i < 8; i++) {
            int c = tid + i * THREADS, row = c >> 3, ch = c & 7;
            cp_async16(base + 2 * MAT_A + row * PITCH + ch * 16,
                       gB + (size_t)row * Kld + k0 + ch * 8);
        }
        asm volatile("cp.async.commit_group;" ::: "memory");
    };

    const int KT = Kloc / BK;
    load_stage(0, 0);
    load_stage(1, BK);

    const uint32_t smb = (uint32_t)__cvta_generic_to_shared(sm);
    const uint32_t a_off = (uint32_t)((lane & 15) * PITCH + (lane >> 4) * 16);
    const uint32_t b_off = (uint32_t)((lane & 7) * PITCH +
                                      ((lane >> 3) & 1) * 16 +
                                      (lane >> 4) * 8 * PITCH);

    int stage = 0;
    for (int kt = 0; kt < KT; kt++) {
        asm volatile("cp.async.wait_group 1;" ::: "memory");
        __syncthreads();
        if (kt + 2 < KT) {
            int s2 = stage + 2; if (s2 >= STAGES) s2 -= STAGES;
            load_stage(s2, (kt + 2) * BK);
        } else {
            asm volatile("cp.async.commit_group;" ::: "memory");
        }

        const uint32_t st  = smb + (uint32_t)(stage * STAGE_B);
        const uint32_t sA0 = st + (uint32_t)((wm * 64) * PITCH);
        const uint32_t sA1 = sA0 + (uint32_t)MAT_A;
        const uint32_t sB  = st + 2u * MAT_A + (uint32_t)((wn * 64) * PITCH);

        #pragma unroll
        for (int ks = 0; ks < 4; ks++) {
            const uint32_t kb = (uint32_t)(ks * 32);
            uint32_t bf[8][2];
            #pragma unroll
            for (int np = 0; np < 4; np++) {
                uint32_t t4[4];
                ldm_x4(t4, sB + (uint32_t)(np * 16 * PITCH) + b_off + kb);
                bf[2 * np][0] = t4[0]; bf[2 * np][1] = t4[1];
                bf[2 * np + 1][0] = t4[2]; bf[2 * np + 1][1] = t4[3];
            }
            uint32_t af[4][4];
            #pragma unroll
            for (int mi = 0; mi < 4; mi++)
                ldm_x4(af[mi], sA0 + (uint32_t)(mi * 16 * PITCH) + a_off + kb);
            #pragma unroll
            for (int mi = 0; mi < 4; mi++)
                #pragma unroll
                for (int ni = 0; ni < 8; ni++)
                    mma16816(acc[mi][ni], af[mi], bf[ni]);
            #pragma unroll
            for (int mi = 0; mi < 4; mi++)
                ldm_x4(af[mi], sA1 + (uint32_t)(mi * 16 * PITCH) + a_off + kb);
            #pragma unroll
            for (int mi = 0; mi < 4; mi++)
                #pragma unroll
                for (int ni = 0; ni < 8; ni++)
                    mma16816(acc[mi][ni], af[mi], bf[ni]);
        }
        if (++stage == STAGES) stage = 0;
    }

    const int r0b = (int)bm + wm * 64;
    const int c0b = (int)bn + wn * 64;
    #pragma unroll
    for (int mi = 0; mi < 4; mi++) {
        const int r0 = r0b + mi * 16 + (lane >> 2);
        #pragma unroll
        for (int ni = 0; ni < 8; ni++) {
            const int c0 = c0b + ni * 8 + (lane & 3) * 2;
            const float s0 = __ldg(scale + c0), s1 = __ldg(scale + c0 + 1);
            atomicAdd(C + (size_t)r0 * N + c0,           acc[mi][ni][0] * s0);
            atomicAdd(C + (size_t)r0 * N + c0 + 1,       acc[mi][ni][1] * s1);
            atomicAdd(C + (size_t)(r0 + 8) * N + c0,     acc[mi][ni][2] * s0);
            atomicAdd(C + (size_t)(r0 + 8) * N + c0 + 1, acc[mi][ni][3] * s1);
        }
    }
}

// zero the output accumulator
__global__ void k_zero(float4* __restrict__ p, int n4) {
    int i = blockIdx.x * blockDim.x + threadIdx.x;
    int stride = gridDim.x * blockDim.x;
    for (; i < n4; i += stride)
        p[i] = make_float4(0.f, 0.f, 0.f, 0.f);
}

// ---------------------------------------------------------------------------
// Elementwise prep kernels
// ---------------------------------------------------------------------------
__global__ void k_convert_w(const int4* __restrict__ wq,
                            __nv_bfloat162* __restrict__ out, int n4) {
    int i = (blockIdx.x * blockDim.x + threadIdx.x) * 4;
    int stride = gridDim.x * blockDim.x * 4;
    for (; i < n4; i += stride) {
        int4 v[4];
        #pragma unroll
        for (int j = 0; j < 4; j++) v[j] = wq[i + j];
        #pragma unroll
        for (int j = 0; j < 4; j++) {
            out[2 * (i + j) + 0] =
                __halves2bfloat162(__float2bfloat16_rn((float)v[j].x),
                                   __float2bfloat16_rn((float)v[j].y));
            out[2 * (i + j) + 1] =
                __halves2bfloat162(__float2bfloat16_rn((float)v[j].z),
                                   __float2bfloat16_rn((float)v[j].w));
        }
    }
}

__global__ void k_split_x(const float4* __restrict__ x,
                          __nv_bfloat162* __restrict__ hi,
                          __nv_bfloat162* __restrict__ lo, int n4) {
    int i = blockIdx.x * blockDim.x + threadIdx.x;
    int stride = gridDim.x * blockDim.x;
    for (; i < n4; i += stride) {
        float4 v = x[i];
        __nv_bfloat16 h0, l0, h1, l1, h2, l2, h3, l3;
        split1(v.x, h0, l0); split1(v.y, h1, l1);
        split1(v.z, h2, l2); split1(v.w, h3, l3);
        hi[2 * i + 0] = __halves2bfloat162(h0, h1);
        hi[2 * i + 1] = __halves2bfloat162(h2, h3);
        lo[2 * i + 0] = __halves2bfloat162(l0, l1);
        lo[2 * i + 1] = __halves2bfloat162(l2, l3);
    }
}

// ---------------------------------------------------------------------------
// Launch
// ---------------------------------------------------------------------------
extern "C" void kernel_launch(void* const* d_in, const int* in_sizes, int n_in,
                              void* d_out, int out_size) {
    const float* x   = (const float*)d_in[0];
    const int*   gwq = (const int*)  d_in[1];
    const float* gsc = (const float*)d_in[2];
    const int*   uwq = (const int*)  d_in[3];
    const float* usc = (const float*)d_in[4];
    const int*   dwq = (const int*)  d_in[5];
    const float* dsc = (const float*)d_in[6];
    float* out = (float*)d_out;

    cudaFuncSetAttribute(k_gemm_sk, cudaFuncAttributeMaxDynamicSharedMemorySize, SMEM_B);
    cudaFuncSetAttribute(k_gemm_gu, cudaFuncAttributeMaxDynamicSharedMemorySize, SMEM2);

    __nv_bfloat16 *wg, *wu, *wd, *xhi, *xlo, *hhi, *hlo;
    cudaGetSymbolAddress((void**)&wg,  g_wg);
    cudaGetSymbolAddress((void**)&wu,  g_wu);
    cudaGetSymbolAddress((void**)&wd,  g_wd);
    cudaGetSymbolAddress((void**)&xhi, g_xhi);
    cudaGetSymbolAddress((void**)&xlo, g_xlo);
    cudaGetSymbolAddress((void**)&hhi, g_hhi);
    cudaGetSymbolAddress((void**)&hlo, g_hlo);

    const int CT = 256;
    {
        int n4 = IDIM * HDIM / 4;
        k_convert_w<<<4096, CT>>>((const int4*)gwq, (__nv_bfloat162*)wg, n4);
        k_convert_w<<<4096, CT>>>((const int4*)uwq, (__nv_bfloat162*)wu, n4);
        k_convert_w<<<4096, CT>>>((const int4*)dwq, (__nv_bfloat162*)wd, n4);
    }
    k_split_x<<<4096, CT>>>((const float4*)x, (__nv_bfloat162*)xhi,
                            (__nv_bfloat162*)xlo, MDIM * HDIM / 4);
    k_zero<<<2048, CT>>>((float4*)out, MDIM * HDIM / 4);

    dim3 grid1(MDIM / 64, IDIM / 128);    // (64, 112), m fastest for W-slab L2 reuse
    k_gemm_gu<<<grid1, THREADS, SMEM2>>>(xhi, xlo, wg, wu, gsc, usc, hhi, hlo, HDIM);

    dim3 grid2(MDIM / BM, HDIM / BN, 2);  // (32, 16, 2) split-K -> RED.ADD
    k_gemm_sk<<<grid2, THREADS, SMEM_B>>>(hhi, hlo, wd, dsc, out,
                                          HDIM, IDIM, IDIM / 2);
}

// round 12
// speedup vs baseline: 1.0990x; 1.0990x over previous
#include <cuda_runtime.h>
#include <cuda_bf16.h>
#include <cstdint>

// ---------------------------------------------------------------------------
// MistralQuantizedMLP via bf16 hi/lo split GEMMs on legacy HMMA
// (mma.sync.m16n8k16.bf16) — only fast tensor path from compute_103 PTX.
//
// R11 = R9 structure (validated 7049us) + ILP-4 weight convert only.
//   gu: fused gate+up GEMM, CTA 128x(128 pair), warp 64x(32 pair),
//       SwiGLU + hi/lo split epilogue.
//   down: split-K=2, fp32 partial buffers + k_add combine.
// ---------------------------------------------------------------------------

static constexpr int MDIM = 4096, HDIM = 4096, IDIM = 14336;
static constexpr int THREADS = 256;
static constexpr int PITCH = 144;               // 128B row + 16B pad

// ---- down-GEMM geometry: CTA 128x256, warp 64x64 ----
static constexpr int BM = 128, BN = 256, BK = 64;
static constexpr int MAT_A = BM * PITCH;            // 18432
static constexpr int MAT_B = BN * PITCH;            // 36864
static constexpr int STAGE_B = 2 * MAT_A + MAT_B;   // 73728
static constexpr int STAGES = 3;
static constexpr int SMEM_B = STAGES * STAGE_B;     // 221184

// ---- fused gate/up geometry: CTA 128x(128 pair), warp 64x(32 pair) ----
static constexpr int MAT2 = 128 * PITCH;            // 18432
static constexpr int STAGE2 = 4 * MAT2;             // A0,A1,Bg,Bu = 73728
static constexpr int SMEM2 = STAGES * STAGE2;       // 221184

// ---- static device scratch (allocation-free rule) ----
__device__ __align__(1024) __nv_bfloat16 g_wg[(size_t)IDIM * HDIM];
__device__ __align__(1024) __nv_bfloat16 g_wu[(size_t)IDIM * HDIM];
__device__ __align__(1024) __nv_bfloat16 g_wd[(size_t)HDIM * IDIM];
__device__ __align__(1024) __nv_bfloat16 g_xhi[(size_t)MDIM * HDIM];
__device__ __align__(1024) __nv_bfloat16 g_xlo[(size_t)MDIM * HDIM];
__device__ __align__(1024) __nv_bfloat16 g_hhi[(size_t)MDIM * IDIM];
__device__ __align__(1024) __nv_bfloat16 g_hlo[(size_t)MDIM * IDIM];
__device__ __align__(1024) float         g_part[2 * (size_t)MDIM * HDIM];

// ---------------------------------------------------------------------------
// PTX helpers
// ---------------------------------------------------------------------------
__device__ __forceinline__ void cp_async16(void* sdst, const void* gsrc) {
    uint32_t s = (uint32_t)__cvta_generic_to_shared(sdst);
    asm volatile("cp.async.cg.shared.global [%0], [%1], 16;" :: "r"(s), "l"(gsrc));
}
__device__ __forceinline__ void ldm_x4(uint32_t* a, uint32_t addr) {
    asm volatile("ldmatrix.sync.aligned.m8n8.x4.shared.b16 {%0,%1,%2,%3}, [%4];"
                 : "=r"(a[0]), "=r"(a[1]), "=r"(a[2]), "=r"(a[3]) : "r"(addr));
}
__device__ __forceinline__ void mma16816(float* c, const uint32_t* a, const uint32_t* b) {
    asm volatile("mma.sync.aligned.m16n8k16.row.col.f32.bf16.bf16.f32 "
                 "{%0,%1,%2,%3}, {%4,%5,%6,%7}, {%8,%9}, {%0,%1,%2,%3};"
                 : "+f"(c[0]), "+f"(c[1]), "+f"(c[2]), "+f"(c[3])
                 : "r"(a[0]), "r"(a[1]), "r"(a[2]), "r"(a[3]), "r"(b[0]), "r"(b[1]));
}
__device__ __forceinline__ void split1(float v, __nv_bfloat16& h, __nv_bfloat16& l) {
    h = __float2bfloat16_rn(v);
    l = __float2bfloat16_rn(v - __bfloat162float(h));
}
__device__ __forceinline__ float silu_f(float g) { return g / (1.0f + expf(-g)); }

// ---------------------------------------------------------------------------
// Fused gate+up GEMM + SwiGLU + hi/lo split epilogue (R8/R9, proven).
// CTA: M=128, N=128 (both matrices). Warp: 64 x 32 pair. 8 warps.
// ---------------------------------------------------------------------------
__global__ __launch_bounds__(THREADS, 1)
void k_gemm_gu(const __nv_bfloat16* __restrict__ Ahi,
               const __nv_bfloat16* __restrict__ Alo,
               const __nv_bfloat16* __restrict__ Bg,
               const __nv_bfloat16* __restrict__ Bu,
               const float* __restrict__ gs, const float* __restrict__ us,
               __nv_bfloat16* __restrict__ Hhi, __nv_bfloat16* __restrict__ Hlo,
               int K) {
    extern __shared__ __align__(128) int8_t sm[];
    const int tid = threadIdx.x, lane = tid & 31, wid = tid >> 5;
    const int wm = wid >> 2, wn = wid & 3;
    const size_t bm = (size_t)blockIdx.x * 128;
    const size_t bn = (size_t)blockIdx.y * 128;

    const __nv_bfloat16* gA0 = Ahi + bm * K;
    const __nv_bfloat16* gA1 = Alo + bm * K;
    const __nv_bfloat16* gBg = Bg + bn * K;
    const __nv_bfloat16* gBu = Bu + bn * K;

    float accg[4][4][4], accu[4][4][4];
    #pragma unroll
    for (int i = 0; i < 4; i++)
        #pragma unroll
        for (int j = 0; j < 4; j++)
            #pragma unroll
            for (int r = 0; r < 4; r++) { accg[i][j][r] = 0.f; accu[i][j][r] = 0.f; }

    auto load_stage = [&](int s, int k0) {
        int8_t* base = sm + s * STAGE2;
        #pragma unroll
        for (int i = 0; i < 4; i++) {
            int c = tid + i * THREADS, row = c >> 3, ch = c & 7;
            cp_async16(base + row * PITCH + ch * 16, gA0 + (size_t)row * K + k0 + ch * 8);
        }
        #pragma unroll
        for (int i = 0; i < 4; i++) {
            int c = tid + i * THREADS, row = c >> 3, ch = c & 7;
            cp_async16(base + MAT2 + row * PITCH + ch * 16,
                       gA1 + (size_t)row * K + k0 + ch * 8);
        }
        #pragma unroll
        for (int i = 0; i < 4; i++) {
            int c = tid + i * THREADS, row = c >> 3, ch = c & 7;
            cp_async16(base + 2 * MAT2 + row * PITCH + ch * 16,
                       gBg + (size_t)row * K + k0 + ch * 8);
        }
        #pragma unroll
        for (int i = 0; i < 4; i++) {
            int c = tid + i * THREADS, row = c >> 3, ch = c & 7;
            cp_async16(base + 3 * MAT2 + row * PITCH + ch * 16,
                       gBu + (size_t)row * K + k0 + ch * 8);
        }
        asm volatile("cp.async.commit_group;" ::: "memory");
    };

    const int KT = K / BK;
    load_stage(0, 0);
    load_stage(1, BK);

    const uint32_t smb = (uint32_t)__cvta_generic_to_shared(sm);
    const uint32_t a_off = (uint32_t)((lane & 15) * PITCH + (lane >> 4) * 16);
    const uint32_t b_off = (uint32_t)((lane & 7) * PITCH +
                                      ((lane >> 3) & 1) * 16 +
                                      (lane >> 4) * 8 * PITCH);

    int stage = 0;
    for (int kt = 0; kt < KT; kt++) {
        asm volatile("cp.async.wait_group 1;" ::: "memory");
        __syncthreads();
        if (kt + 2 < KT) {
            int s2 = stage + 2; if (s2 >= STAGES) s2 -= STAGES;
            load_stage(s2, (kt + 2) * BK);
        } else {
            asm volatile("cp.async.commit_group;" ::: "memory");
        }

        const uint32_t st  = smb + (uint32_t)(stage * STAGE2);
        const uint32_t sA0 = st + (uint32_t)((wm * 64) * PITCH);
        const uint32_t sA1 = sA0 + (uint32_t)MAT2;
        const uint32_t sBg = st + 2u * MAT2 + (uint32_t)((wn * 32) * PITCH);
        const uint32_t sBu = st + 3u * MAT2 + (uint32_t)((wn * 32) * PITCH);

        #pragma unroll
        for (int ks = 0; ks < 4; ks++) {
            const uint32_t kb = (uint32_t)(ks * 32);
            uint32_t bg[4][2], bu[4][2];
            #pragma unroll
            for (int np = 0; np < 2; np++) {
                uint32_t t4[4];
                ldm_x4(t4, sBg + (uint32_t)(np * 16 * PITCH) + b_off + kb);
                bg[2*np][0] = t4[0]; bg[2*np][1] = t4[1];
                bg[2*np+1][0] = t4[2]; bg[2*np+1][1] = t4[3];
                ldm_x4(t4, sBu + (uint32_t)(np * 16 * PITCH) + b_off + kb);
                bu[2*np][0] = t4[0]; bu[2*np][1] = t4[1];
                bu[2*np+1][0] = t4[2]; bu[2*np+1][1] = t4[3];
            }
            uint32_t af[4][4];
            #pragma unroll
            for (int mi = 0; mi < 4; mi++)
                ldm_x4(af[mi], sA0 + (uint32_t)(mi * 16 * PITCH) + a_off + kb);
            #pragma unroll
            for (int mi = 0; mi < 4; mi++)
                #pragma unroll
                for (int ni = 0; ni < 4; ni++) {
                    mma16816(accg[mi][ni], af[mi], bg[ni]);
                    mma16816(accu[mi][ni], af[mi], bu[ni]);
                }
            #pragma unroll
            for (int mi = 0; mi < 4; mi++)
                ldm_x4(af[mi], sA1 + (uint32_t)(mi * 16 * PITCH) + a_off + kb);
            #pragma unroll
            for (int mi = 0; mi < 4; mi++)
                #pragma unroll
                for (int ni = 0; ni < 4; ni++) {
                    mma16816(accg[mi][ni], af[mi], bg[ni]);
                    mma16816(accu[mi][ni], af[mi], bu[ni]);
                }
        }
        if (++stage == STAGES) stage = 0;
    }

    const int r0b = (int)bm + wm * 64;
    const int c0b = (int)bn + wn * 32;
    #pragma unroll
    for (int mi = 0; mi < 4; mi++) {
        const int r0 = r0b + mi * 16 + (lane >> 2);
        #pragma unroll
        for (int ni = 0; ni < 4; ni++) {
            const int c0 = c0b + ni * 8 + (lane & 3) * 2;
            const float gs0 = __ldg(gs + c0), gs1 = __ldg(gs + c0 + 1);
            const float us0 = __ldg(us + c0), us1 = __ldg(us + c0 + 1);
            float h00 = silu_f(accg[mi][ni][0] * gs0) * (accu[mi][ni][0] * us0);
            float h01 = silu_f(accg[mi][ni][1] * gs1) * (accu[mi][ni][1] * us1);
            float h10 = silu_f(accg[mi][ni][2] * gs0) * (accu[mi][ni][2] * us0);
            float h11 = silu_f(accg[mi][ni][3] * gs1) * (accu[mi][ni][3] * us1);
            __nv_bfloat16 a0, b0, a1, b1, a2, b2, a3, b3;
            split1(h00, a0, b0); split1(h01, a1, b1);
            split1(h10, a2, b2); split1(h11, a3, b3);
            *reinterpret_cast<__nv_bfloat162*>(Hhi + (size_t)r0 * IDIM + c0) =
                __halves2bfloat162(a0, a1);
            *reinterpret_cast<__nv_bfloat162*>(Hlo + (size_t)r0 * IDIM + c0) =
                __halves2bfloat162(b0, b1);
            *reinterpret_cast<__nv_bfloat162*>(Hhi + (size_t)(r0 + 8) * IDIM + c0) =
                __halves2bfloat162(a2, a3);
            *reinterpret_cast<__nv_bfloat162*>(Hlo + (size_t)(r0 + 8) * IDIM + c0) =
                __halves2bfloat162(b2, b3);
        }
    }
}

// ---------------------------------------------------------------------------
// Down GEMM, split-K=2 (R9, proven): partial C per z-slice.
// ---------------------------------------------------------------------------
__global__ __launch_bounds__(THREADS, 1)
void k_gemm_sk(const __nv_bfloat16* __restrict__ Ahi,
               const __nv_bfloat16* __restrict__ Alo,
               const __nv_bfloat16* __restrict__ Bw,
               const float* __restrict__ scale,
               float* __restrict__ Cpart, int N, int Kld, int Kloc) {
    extern __shared__ __align__(128) int8_t sm[];
    const int tid = threadIdx.x, lane = tid & 31, wid = tid >> 5;
    const int wm = wid >> 2, wn = wid & 3;
    const size_t bm = (size_t)blockIdx.x * BM;
    const size_t bn = (size_t)blockIdx.y * BN;
    const int k0g = blockIdx.z * Kloc;

    const __nv_bfloat16* gA0 = Ahi + bm * Kld + k0g;
    const __nv_bfloat16* gA1 = Alo + bm * Kld + k0g;
    const __nv_bfloat16* gB  = Bw  + bn * Kld + k0g;
    float* C = Cpart + (size_t)blockIdx.z * MDIM * HDIM;

    float acc[4][8][4];
    #pragma unroll
    for (int i = 0; i < 4; i++)
        #pragma unroll
        for (int j = 0; j < 8; j++)
            #pragma unroll
            for (int r = 0; r < 4; r++) acc[i][j][r] = 0.0f;

    auto load_stage = [&](int s, int k0) {
        int8_t* base = sm + s * STAGE_B;
        #pragma unroll
        for (int i = 0; i < 4; i++) {
            int c = tid + i * THREADS, row = c >> 3, ch = c & 7;
            cp_async16(base + row * PITCH + ch * 16,
                       gA0 + (size_t)row * Kld + k0 + ch * 8);
        }
        #pragma unroll
        for (int i = 0; i < 4; i++) {
            int c = tid + i * THREADS, row = c >> 3, ch = c & 7;
            cp_async16(base + MAT_A + row * PITCH + ch * 16,
                       gA1 + (size_t)row * Kld + k0 + ch * 8);
        }
        #pragma unroll
        for (int i = 0; i < 8; i++) {
            int c = tid + i * THREADS, row = c >> 3, ch = c & 7;
            cp_async16(base + 2 * MAT_A + row * PITCH + ch * 16,
                       gB + (size_t)row * Kld + k0 + ch * 8);
        }
        asm volatile("cp.async.commit_group;" ::: "memory");
    };

    const int KT = Kloc / BK;
    load_stage(0, 0);
    load_stage(1, BK);

    const uint32_t smb = (uint32_t)__cvta_generic_to_shared(sm);
    const uint32_t a_off = (uint32_t)((lane & 15) * PITCH + (lane >> 4) * 16);
    const uint32_t b_off = (uint32_t)((lane & 7) * PITCH +
                                      ((lane >> 3) & 1) * 16 +
                                      (lane >> 4) * 8 * PITCH);

    int stage = 0;
    for (int kt = 0; kt < KT; kt++) {
        asm volatile("cp.async.wait_group 1;" ::: "memory");
        __syncthreads();
        if (kt + 2 < KT) {
            int s2 = stage + 2; if (s2 >= STAGES) s2 -= STAGES;
            load_stage(s2, (kt + 2) * BK);
        } else {
            asm volatile("cp.async.commit_group;" ::: "memory");
        }

        const uint32_t st  = smb + (uint32_t)(stage * STAGE_B);
        const uint32_t sA0 = st + (uint32_t)((wm * 64) * PITCH);
        const uint32_t sA1 = sA0 + (uint32_t)MAT_A;
        const uint32_t sB  = st + 2u * MAT_A + (uint32_t)((wn * 64) * PITCH);

        #pragma unroll
        for (int ks = 0; ks < 4; ks++) {
            const uint32_t kb = (uint32_t)(ks * 32);
            uint32_t bf[8][2];
            #pragma unroll
            for (int np = 0; np < 4; np++) {
                uint32_t t4[4];
                ldm_x4(t4, sB + (uint32_t)(np * 16 * PITCH) + b_off + kb);
                bf[2 * np][0] = t4[0]; bf[2 * np][1] = t4[1];
                bf[2 * np + 1][0] = t4[2]; bf[2 * np + 1][1] = t4[3];
            }
            uint32_t af[4][4];
            #pragma unroll
            for (int mi = 0; mi < 4; mi++)
                ldm_x4(af[mi], sA0 + (uint32_t)(mi * 16 * PITCH) + a_off + kb);
            #pragma unroll
            for (int mi = 0; mi < 4; mi++)
                #pragma unroll
                for (int ni = 0; ni < 8; ni++)
                    mma16816(acc[mi][ni], af[mi], bf[ni]);
            #pragma unroll
            for (int mi = 0; mi < 4; mi++)
                ldm_x4(af[mi], sA1 + (uint32_t)(mi * 16 * PITCH) + a_off + kb);
            #pragma unroll
            for (int mi = 0; mi < 4; mi++)
                #pragma unroll
                for (int ni = 0; ni < 8; ni++)
                    mma16816(acc[mi][ni], af[mi], bf[ni]);
        }
        if (++stage == STAGES) stage = 0;
    }

    const int r0b = (int)bm + wm * 64;
    const int c0b = (int)bn + wn * 64;
    #pragma unroll
    for (int mi = 0; mi < 4; mi++) {
        const int r0 = r0b + mi * 16 + (lane >> 2);
        #pragma unroll
        for (int ni = 0; ni < 8; ni++) {
            const int c0 = c0b + ni * 8 + (lane & 3) * 2;
            const float s0 = __ldg(scale + c0), s1 = __ldg(scale + c0 + 1);
            float2 v0 = make_float2(acc[mi][ni][0] * s0, acc[mi][ni][1] * s1);
            float2 v1 = make_float2(acc[mi][ni][2] * s0, acc[mi][ni][3] * s1);
            *reinterpret_cast<float2*>(C + (size_t)r0 * N + c0) = v0;
            *reinterpret_cast<float2*>(C + (size_t)(r0 + 8) * N + c0) = v1;
        }
    }
}

// combine the two split-K partials
__global__ void k_add(const float4* __restrict__ p0, const float4* __restrict__ p1,
                      float4* __restrict__ out, int n4) {
    int i = blockIdx.x * blockDim.x + threadIdx.x;
    int stride = gridDim.x * blockDim.x;
    for (; i < n4; i += stride) {
        float4 a = p0[i], b = p1[i];
        out[i] = make_float4(a.x + b.x, a.y + b.y, a.z + b.z, a.w + b.w);
    }
}

// ---------------------------------------------------------------------------
// Elementwise prep kernels
// ---------------------------------------------------------------------------
__global__ void k_convert_w(const int4* __restrict__ wq,
                            __nv_bfloat162* __restrict__ out, int n4) {
    int i = (blockIdx.x * blockDim.x + threadIdx.x) * 4;
    int stride = gridDim.x * blockDim.x * 4;
    for (; i < n4; i += stride) {
        int4 v[4];
        #pragma unroll
        for (int j = 0; j < 4; j++) v[j] = wq[i + j];
        #pragma unroll
        for (int j = 0; j < 4; j++) {
            out[2 * (i + j) + 0] =
                __halves2bfloat162(__float2bfloat16_rn((float)v[j].x),
                                   __float2bfloat16_rn((float)v[j].y));
            out[2 * (i + j) + 1] =
                __halves2bfloat162(__float2bfloat16_rn((float)v[j].z),
                                   __float2bfloat16_rn((float)v[j].w));
        }
    }
}

__global__ void k_split_x(const float4* __restrict__ x,
                          __nv_bfloat162* __restrict__ hi,
                          __nv_bfloat162* __restrict__ lo, int n4) {
    int i = blockIdx.x * blockDim.x + threadIdx.x;
    int stride = gridDim.x * blockDim.x;
    for (; i < n4; i += stride) {
        float4 v = x[i];
        __nv_bfloat16 h0, l0, h1, l1, h2, l2, h3, l3;
        split1(v.x, h0, l0); split1(v.y, h1, l1);
        split1(v.z, h2, l2); split1(v.w, h3, l3);
        hi[2 * i + 0] = __halves2bfloat162(h0, h1);
        hi[2 * i + 1] = __halves2bfloat162(h2, h3);
        lo[2 * i + 0] = __halves2bfloat162(l0, l1);
        lo[2 * i + 1] = __halves2bfloat162(l2, l3);
    }
}

// ---------------------------------------------------------------------------
// Launch
// ---------------------------------------------------------------------------
extern "C" void kernel_launch(void* const* d_in, const int* in_sizes, int n_in,
                              void* d_out, int out_size) {
    const float* x   = (const float*)d_in[0];
    const int*   gwq = (const int*)  d_in[1];
    const float* gsc = (const float*)d_in[2];
    const int*   uwq = (const int*)  d_in[3];
    const float* usc = (const float*)d_in[4];
    const int*   dwq = (const int*)  d_in[5];
    const float* dsc = (const float*)d_in[6];
    float* out = (float*)d_out;

    cudaFuncSetAttribute(k_gemm_sk, cudaFuncAttributeMaxDynamicSharedMemorySize, SMEM_B);
    cudaFuncSetAttribute(k_gemm_gu, cudaFuncAttributeMaxDynamicSharedMemorySize, SMEM2);

    __nv_bfloat16 *wg, *wu, *wd, *xhi, *xlo, *hhi, *hlo;
    float *part;
    cudaGetSymbolAddress((void**)&wg,  g_wg);
    cudaGetSymbolAddress((void**)&wu,  g_wu);
    cudaGetSymbolAddress((void**)&wd,  g_wd);
    cudaGetSymbolAddress((void**)&xhi, g_xhi);
    cudaGetSymbolAddress((void**)&xlo, g_xlo);
    cudaGetSymbolAddress((void**)&hhi, g_hhi);
    cudaGetSymbolAddress((void**)&hlo, g_hlo);
    cudaGetSymbolAddress((void**)&part, g_part);

    const int CT = 256;
    {
        int n4 = IDIM * HDIM / 4;
        k_convert_w<<<4096, CT>>>((const int4*)gwq, (__nv_bfloat162*)wg, n4);
        k_convert_w<<<4096, CT>>>((const int4*)uwq, (__nv_bfloat162*)wu, n4);
        k_convert_w<<<4096, CT>>>((const int4*)dwq, (__nv_bfloat162*)wd, n4);
    }
    k_split_x<<<4096, CT>>>((const float4*)x, (__nv_bfloat162*)xhi,
                            (__nv_bfloat162*)xlo, MDIM * HDIM / 4);

    dim3 grid1(MDIM / 128, IDIM / 128);   // (32, 112), m fastest for W-slab L2 reuse
    k_gemm_gu<<<grid1, THREADS, SMEM2>>>(xhi, xlo, wg, wu, gsc, usc, hhi, hlo, HDIM);

    dim3 grid2(MDIM / BM, HDIM / BN, 2);  // (32, 16, 2) split-K
    k_gemm_sk<<<grid2, THREADS, SMEM_B>>>(hhi, hlo, wd, dsc, part,
                                          HDIM, IDIM, IDIM / 2);

    k_add<<<2048, CT>>>((const float4*)part,
                        (const float4*)(part + (size_t)MDIM * HDIM),
                        (float4*)out, MDIM * HDIM / 4);
}

// round 14
// speedup vs baseline: 1.1290x; 1.0273x over previous
#include <cuda_runtime.h>
#include <cuda_bf16.h>
#include <cstdint>

// ---------------------------------------------------------------------------
// MistralQuantizedMLP via bf16 hi/lo split GEMMs on legacy HMMA
// (mma.sync.m16n8k16.bf16) — only fast tensor path from compute_103 PTX.
//
// R13 = R9 (validated 7049us) with converts fixed: range-split ILP-2,
// fully-coalesced loads AND packed uint2 stores.
//   gu: fused gate+up GEMM, CTA 128x(128 pair), warp 64x(32 pair),
//       SwiGLU + hi/lo split epilogue.
//   down: split-K=2, fp32 partial buffers + k_add combine.
// ---------------------------------------------------------------------------

static constexpr int MDIM = 4096, HDIM = 4096, IDIM = 14336;
static constexpr int THREADS = 256;
static constexpr int PITCH = 144;               // 128B row + 16B pad

// ---- down-GEMM geometry: CTA 128x256, warp 64x64 ----
static constexpr int BM = 128, BN = 256, BK = 64;
static constexpr int MAT_A = BM * PITCH;            // 18432
static constexpr int MAT_B = BN * PITCH;            // 36864
static constexpr int STAGE_B = 2 * MAT_A + MAT_B;   // 73728
static constexpr int STAGES = 3;
static constexpr int SMEM_B = STAGES * STAGE_B;     // 221184

// ---- fused gate/up geometry: CTA 128x(128 pair), warp 64x(32 pair) ----
static constexpr int MAT2 = 128 * PITCH;            // 18432
static constexpr int STAGE2 = 4 * MAT2;             // A0,A1,Bg,Bu = 73728
static constexpr int SMEM2 = STAGES * STAGE2;       // 221184

// ---- static device scratch (allocation-free rule) ----
__device__ __align__(1024) __nv_bfloat16 g_wg[(size_t)IDIM * HDIM];
__device__ __align__(1024) __nv_bfloat16 g_wu[(size_t)IDIM * HDIM];
__device__ __align__(1024) __nv_bfloat16 g_wd[(size_t)HDIM * IDIM];
__device__ __align__(1024) __nv_bfloat16 g_xhi[(size_t)MDIM * HDIM];
__device__ __align__(1024) __nv_bfloat16 g_xlo[(size_t)MDIM * HDIM];
__device__ __align__(1024) __nv_bfloat16 g_hhi[(size_t)MDIM * IDIM];
__device__ __align__(1024) __nv_bfloat16 g_hlo[(size_t)MDIM * IDIM];
__device__ __align__(1024) float         g_part[2 * (size_t)MDIM * HDIM];

// ---------------------------------------------------------------------------
// PTX helpers
// ---------------------------------------------------------------------------
__device__ __forceinline__ void cp_async16(void* sdst, const void* gsrc) {
    uint32_t s = (uint32_t)__cvta_generic_to_shared(sdst);
    asm volatile("cp.async.cg.shared.global [%0], [%1], 16;" :: "r"(s), "l"(gsrc));
}
__device__ __forceinline__ void ldm_x4(uint32_t* a, uint32_t addr) {
    asm volatile("ldmatrix.sync.aligned.m8n8.x4.shared.b16 {%0,%1,%2,%3}, [%4];"
                 : "=r"(a[0]), "=r"(a[1]), "=r"(a[2]), "=r"(a[3]) : "r"(addr));
}
__device__ __forceinline__ void mma16816(float* c, const uint32_t* a, const uint32_t* b) {
    asm volatile("mma.sync.aligned.m16n8k16.row.col.f32.bf16.bf16.f32 "
                 "{%0,%1,%2,%3}, {%4,%5,%6,%7}, {%8,%9}, {%0,%1,%2,%3};"
                 : "+f"(c[0]), "+f"(c[1]), "+f"(c[2]), "+f"(c[3])
                 : "r"(a[0]), "r"(a[1]), "r"(a[2]), "r"(a[3]), "r"(b[0]), "r"(b[1]));
}
__device__ __forceinline__ void split1(float v, __nv_bfloat16& h, __nv_bfloat16& l) {
    h = __float2bfloat16_rn(v);
    l = __float2bfloat16_rn(v - __bfloat162float(h));
}
__device__ __forceinline__ float silu_f(float g) { return g / (1.0f + expf(-g)); }

// ---------------------------------------------------------------------------
// Fused gate+up GEMM + SwiGLU + hi/lo split epilogue (R8/R9, proven).
// CTA: M=128, N=128 (both matrices). Warp: 64 x 32 pair. 8 warps.
// ---------------------------------------------------------------------------
__global__ __launch_bounds__(THREADS, 1)
void k_gemm_gu(const __nv_bfloat16* __restrict__ Ahi,
               const __nv_bfloat16* __restrict__ Alo,
               const __nv_bfloat16* __restrict__ Bg,
               const __nv_bfloat16* __restrict__ Bu,
               const float* __restrict__ gs, const float* __restrict__ us,
               __nv_bfloat16* __restrict__ Hhi, __nv_bfloat16* __restrict__ Hlo,
               int K) {
    extern __shared__ __align__(128) int8_t sm[];
    const int tid = threadIdx.x, lane = tid & 31, wid = tid >> 5;
    const int wm = wid >> 2, wn = wid & 3;
    const size_t bm = (size_t)blockIdx.x * 128;
    const size_t bn = (size_t)blockIdx.y * 128;

    const __nv_bfloat16* gA0 = Ahi + bm * K;
    const __nv_bfloat16* gA1 = Alo + bm * K;
    const __nv_bfloat16* gBg = Bg + bn * K;
    const __nv_bfloat16* gBu = Bu + bn * K;

    float accg[4][4][4], accu[4][4][4];
    #pragma unroll
    for (int i = 0; i < 4; i++)
        #pragma unroll
        for (int j = 0; j < 4; j++)
            #pragma unroll
            for (int r = 0; r < 4; r++) { accg[i][j][r] = 0.f; accu[i][j][r] = 0.f; }

    auto load_stage = [&](int s, int k0) {
        int8_t* base = sm + s * STAGE2;
        #pragma unroll
        for (int i = 0; i < 4; i++) {
            int c = tid + i * THREADS, row = c >> 3, ch = c & 7;
            cp_async16(base + row * PITCH + ch * 16, gA0 + (size_t)row * K + k0 + ch * 8);
        }
        #pragma unroll
        for (int i = 0; i < 4; i++) {
            int c = tid + i * THREADS, row = c >> 3, ch = c & 7;
            cp_async16(base + MAT2 + row * PITCH + ch * 16,
                       gA1 + (size_t)row * K + k0 + ch * 8);
        }
        #pragma unroll
        for (int i = 0; i < 4; i++) {
            int c = tid + i * THREADS, row = c >> 3, ch = c & 7;
            cp_async16(base + 2 * MAT2 + row * PITCH + ch * 16,
                       gBg + (size_t)row * K + k0 + ch * 8);
        }
        #pragma unroll
        for (int i = 0; i < 4; i++) {
            int c = tid + i * THREADS, row = c >> 3, ch = c & 7;
            cp_async16(base + 3 * MAT2 + row * PITCH + ch * 16,
                       gBu + (size_t)row * K + k0 + ch * 8);
        }
        asm volatile("cp.async.commit_group;" ::: "memory");
    };

    const int KT = K / BK;
    load_stage(0, 0);
    load_stage(1, BK);

    const uint32_t smb = (uint32_t)__cvta_generic_to_shared(sm);
    const uint32_t a_off = (uint32_t)((lane & 15) * PITCH + (lane >> 4) * 16);
    const uint32_t b_off = (uint32_t)((lane & 7) * PITCH +
                                      ((lane >> 3) & 1) * 16 +
                                      (lane >> 4) * 8 * PITCH);

    int stage = 0;
    for (int kt = 0; kt < KT; kt++) {
        asm volatile("cp.async.wait_group 1;" ::: "memory");
        __syncthreads();
        if (kt + 2 < KT) {
            int s2 = stage + 2; if (s2 >= STAGES) s2 -= STAGES;
            load_stage(s2, (kt + 2) * BK);
        } else {
            asm volatile("cp.async.commit_group;" ::: "memory");
        }

        const uint32_t st  = smb + (uint32_t)(stage * STAGE2);
        const uint32_t sA0 = st + (uint32_t)((wm * 64) * PITCH);
        const uint32_t sA1 = sA0 + (uint32_t)MAT2;
        const uint32_t sBg = st + 2u * MAT2 + (uint32_t)((wn * 32) * PITCH);
        const uint32_t sBu = st + 3u * MAT2 + (uint32_t)((wn * 32) * PITCH);

        #pragma unroll
        for (int ks = 0; ks < 4; ks++) {
            const uint32_t kb = (uint32_t)(ks * 32);
            uint32_t bg[4][2], bu[4][2];
            #pragma unroll
            for (int np = 0; np < 2; np++) {
                uint32_t t4[4];
                ldm_x4(t4, sBg + (uint32_t)(np * 16 * PITCH) + b_off + kb);
                bg[2*np][0] = t4[0]; bg[2*np][1] = t4[1];
                bg[2*np+1][0] = t4[2]; bg[2*np+1][1] = t4[3];
                ldm_x4(t4, sBu + (uint32_t)(np * 16 * PITCH) + b_off + kb);
                bu[2*np][0] = t4[0]; bu[2*np][1] = t4[1];
                bu[2*np+1][0] = t4[2]; bu[2*np+1][1] = t4[3];
            }
            uint32_t af[4][4];
            #pragma unroll
            for (int mi = 0; mi < 4; mi++)
                ldm_x4(af[mi], sA0 + (uint32_t)(mi * 16 * PITCH) + a_off + kb);
            #pragma unroll
            for (int mi = 0; mi < 4; mi++)
                #pragma unroll
                for (int ni = 0; ni < 4; ni++) {
                    mma16816(accg[mi][ni], af[mi], bg[ni]);
                    mma16816(accu[mi][ni], af[mi], bu[ni]);
                }
            #pragma unroll
            for (int mi = 0; mi < 4; mi++)
                ldm_x4(af[mi], sA1 + (uint32_t)(mi * 16 * PITCH) + a_off + kb);
            #pragma unroll
            for (int mi = 0; mi < 4; mi++)
                #pragma unroll
                for (int ni = 0; ni < 4; ni++) {
                    mma16816(accg[mi][ni], af[mi], bg[ni]);
                    mma16816(accu[mi][ni], af[mi], bu[ni]);
                }
        }
        if (++stage == STAGES) stage = 0;
    }

    const int r0b = (int)bm + wm * 64;
    const int c0b = (int)bn + wn * 32;
    #pragma unroll
    for (int mi = 0; mi < 4; mi++) {
        const int r0 = r0b + mi * 16 + (lane >> 2);
        #pragma unroll
        for (int ni = 0; ni < 4; ni++) {
            const int c0 = c0b + ni * 8 + (lane & 3) * 2;
            const float gs0 = __ldg(gs + c0), gs1 = __ldg(gs + c0 + 1);
            const float us0 = __ldg(us + c0), us1 = __ldg(us + c0 + 1);
            float h00 = silu_f(accg[mi][ni][0] * gs0) * (accu[mi][ni][0] * us0);
            float h01 = silu_f(accg[mi][ni][1] * gs1) * (accu[mi][ni][1] * us1);
            float h10 = silu_f(accg[mi][ni][2] * gs0) * (accu[mi][ni][2] * us0);
            float h11 = silu_f(accg[mi][ni][3] * gs1) * (accu[mi][ni][3] * us1);
            __nv_bfloat16 a0, b0, a1, b1, a2, b2, a3, b3;
            split1(h00, a0, b0); split1(h01, a1, b1);
            split1(h10, a2, b2); split1(h11, a3, b3);
            *reinterpret_cast<__nv_bfloat162*>(Hhi + (size_t)r0 * IDIM + c0) =
                __halves2bfloat162(a0, a1);
            *reinterpret_cast<__nv_bfloat162*>(Hlo + (size_t)r0 * IDIM + c0) =
                __halves2bfloat162(b0, b1);
            *reinterpret_cast<__nv_bfloat162*>(Hhi + (size_t)(r0 + 8) * IDIM + c0) =
                __halves2bfloat162(a2, a3);
            *reinterpret_cast<__nv_bfloat162*>(Hlo + (size_t)(r0 + 8) * IDIM + c0) =
                __halves2bfloat162(b2, b3);
        }
    }
}

// ---------------------------------------------------------------------------
// Down GEMM, split-K=2 (R9, proven): partial C per z-slice.
// ---------------------------------------------------------------------------
__global__ __launch_bounds__(THREADS, 1)
void k_gemm_sk(const __nv_bfloat16* __restrict__ Ahi,
               const __nv_bfloat16* __restrict__ Alo,
               const __nv_bfloat16* __restrict__ Bw,
               const float* __restrict__ scale,
               float* __restrict__ Cpart, int N, int Kld, int Kloc) {
    extern __shared__ __align__(128) int8_t sm[];
    const int tid = threadIdx.x, lane = tid & 31, wid = tid >> 5;
    const int wm = wid >> 2, wn = wid & 3;
    const size_t bm = (size_t)blockIdx.x * BM;
    const size_t bn = (size_t)blockIdx.y * BN;
    const int k0g = blockIdx.z * Kloc;

    const __nv_bfloat16* gA0 = Ahi + bm * Kld + k0g;
    const __nv_bfloat16* gA1 = Alo + bm * Kld + k0g;
    const __nv_bfloat16* gB  = Bw  + bn * Kld + k0g;
    float* C = Cpart + (size_t)blockIdx.z * MDIM * HDIM;

    float acc[4][8][4];
    #pragma unroll
    for (int i = 0; i < 4; i++)
        #pragma unroll
        for (int j = 0; j < 8; j++)
            #pragma unroll
            for (int r = 0; r < 4; r++) acc[i][j][r] = 0.0f;

    auto load_stage = [&](int s, int k0) {
        int8_t* base = sm + s * STAGE_B;
        #pragma unroll
        for (int i = 0; i < 4; i++) {
            int c = tid + i * THREADS, row = c >> 3, ch = c & 7;
            cp_async16(base + row * PITCH + ch * 16,
                       gA0 + (size_t)row * Kld + k0 + ch * 8);
        }
        #pragma unroll
        for (int i = 0; i < 4; i++) {
            int c = tid + i * THREADS, row = c >> 3, ch = c & 7;
            cp_async16(base + MAT_A + row * PITCH + ch * 16,
                       gA1 + (size_t)row * Kld + k0 + ch * 8);
        }
        #pragma unroll
        for (int i = 0; i < 8; i++) {
            int c = tid + i * THREADS, row = c >> 3, ch = c & 7;
            cp_async16(base + 2 * MAT_A + row * PITCH + ch * 16,
                       gB + (size_t)row * Kld + k0 + ch * 8);
        }
        asm volatile("cp.async.commit_group;" ::: "memory");
    };

    const int KT = Kloc / BK;
    load_stage(0, 0);
    load_stage(1, BK);

    const uint32_t smb = (uint32_t)__cvta_generic_to_shared(sm);
    const uint32_t a_off = (uint32_t)((lane & 15) * PITCH + (lane >> 4) * 16);
    const uint32_t b_off = (uint32_t)((lane & 7) * PITCH +
                                      ((lane >> 3) & 1) * 16 +
                                      (lane >> 4) * 8 * PITCH);

    int stage = 0;
    for (int kt = 0; kt < KT; kt++) {
        asm volatile("cp.async.wait_group 1;" ::: "memory");
        __syncthreads();
        if (kt + 2 < KT) {
            int s2 = stage + 2; if (s2 >= STAGES) s2 -= STAGES;
            load_stage(s2, (kt + 2) * BK);
        } else {
            asm volatile("cp.async.commit_group;" ::: "memory");
        }

        const uint32_t st  = smb + (uint32_t)(stage * STAGE_B);
        const uint32_t sA0 = st + (uint32_t)((wm * 64) * PITCH);
        const uint32_t sA1 = sA0 + (uint32_t)MAT_A;
        const uint32_t sB  = st + 2u * MAT_A + (uint32_t)((wn * 64) * PITCH);

        #pragma unroll
        for (int ks = 0; ks < 4; ks++) {
            const uint32_t kb = (uint32_t)(ks * 32);
            uint32_t bf[8][2];
            #pragma unroll
            for (int np = 0; np < 4; np++) {
                uint32_t t4[4];
                ldm_x4(t4, sB + (uint32_t)(np * 16 * PITCH) + b_off + kb);
                bf[2 * np][0] = t4[0]; bf[2 * np][1] = t4[1];
                bf[2 * np + 1][0] = t4[2]; bf[2 * np + 1][1] = t4[3];
            }
            uint32_t af[4][4];
            #pragma unroll
            for (int mi = 0; mi < 4; mi++)
                ldm_x4(af[mi], sA0 + (uint32_t)(mi * 16 * PITCH) + a_off + kb);
            #pragma unroll
            for (int mi = 0; mi < 4; mi++)
                #pragma unroll
                for (int ni = 0; ni < 8; ni++)
                    mma16816(acc[mi][ni], af[mi], bf[ni]);
            #pragma unroll
            for (int mi = 0; mi < 4; mi++)
                ldm_x4(af[mi], sA1 + (uint32_t)(mi * 16 * PITCH) + a_off + kb);
            #pragma unroll
            for (int mi = 0; mi < 4; mi++)
                #pragma unroll
                for (int ni = 0; ni < 8; ni++)
                    mma16816(acc[mi][ni], af[mi], bf[ni]);
        }
        if (++stage == STAGES) stage = 0;
    }

    const int r0b = (int)bm + wm * 64;
    const int c0b = (int)bn + wn * 64;
    #pragma unroll
    for (int mi = 0; mi < 4; mi++) {
        const int r0 = r0b + mi * 16 + (lane >> 2);
        #pragma unroll
        for (int ni = 0; ni < 8; ni++) {
            const int c0 = c0b + ni * 8 + (lane & 3) * 2;
            const float s0 = __ldg(scale + c0), s1 = __ldg(scale + c0 + 1);
            float2 v0 = make_float2(acc[mi][ni][0] * s0, acc[mi][ni][1] * s1);
            float2 v1 = make_float2(acc[mi][ni][2] * s0, acc[mi][ni][3] * s1);
            *reinterpret_cast<float2*>(C + (size_t)r0 * N + c0) = v0;
            *reinterpret_cast<float2*>(C + (size_t)(r0 + 8) * N + c0) = v1;
        }
    }
}

// combine the two split-K partials
__global__ void k_add(const float4* __restrict__ p0, const float4* __restrict__ p1,
                      float4* __restrict__ out, int n4) {
    int i = blockIdx.x * blockDim.x + threadIdx.x;
    int stride = gridDim.x * blockDim.x;
    for (; i < n4; i += stride) {
        float4 a = p0[i], b = p1[i];
        out[i] = make_float4(a.x + b.x, a.y + b.y, a.z + b.z, a.w + b.w);
    }
}

// ---------------------------------------------------------------------------
// Elementwise prep kernels
// ---------------------------------------------------------------------------
// Range-split ILP-2: both loads and both (packed) stores are fully
// lane-contiguous; MLP=2 without any coalescing loss.
__global__ void k_convert_w(const int4* __restrict__ wq,
                            uint2* __restrict__ out, int n4) {
    const int n2 = n4 >> 1;
    int i = blockIdx.x * blockDim.x + threadIdx.x;
    int stride = gridDim.x * blockDim.x;
    for (; i < n2; i += stride) {
        int4 v0 = wq[i];
        int4 v1 = wq[i + n2];
        __nv_bfloat162 a0 = __halves2bfloat162(__float2bfloat16_rn((float)v0.x),
                                               __float2bfloat16_rn((float)v0.y));
        __nv_bfloat162 a1 = __halves2bfloat162(__float2bfloat16_rn((float)v0.z),
                                               __float2bfloat16_rn((float)v0.w));
        __nv_bfloat162 b0 = __halves2bfloat162(__float2bfloat16_rn((float)v1.x),
                                               __float2bfloat16_rn((float)v1.y));
        __nv_bfloat162 b1 = __halves2bfloat162(__float2bfloat16_rn((float)v1.z),
                                               __float2bfloat16_rn((float)v1.w));
        out[i]      = make_uint2(*reinterpret_cast<uint32_t*>(&a0),
                                 *reinterpret_cast<uint32_t*>(&a1));
        out[i + n2] = make_uint2(*reinterpret_cast<uint32_t*>(&b0),
                                 *reinterpret_cast<uint32_t*>(&b1));
    }
}

__global__ void k_split_x(const float4* __restrict__ x,
                          __nv_bfloat162* __restrict__ hi,
                          __nv_bfloat162* __restrict__ lo, int n4) {
    int i = blockIdx.x * blockDim.x + threadIdx.x;
    int stride = gridDim.x * blockDim.x;
    for (; i < n4; i += stride) {
        float4 v = x[i];
        __nv_bfloat16 h0, l0, h1, l1, h2, l2, h3, l3;
        split1(v.x, h0, l0); split1(v.y, h1, l1);
        split1(v.z, h2, l2); split1(v.w, h3, l3);
        hi[2 * i + 0] = __halves2bfloat162(h0, h1);
        hi[2 * i + 1] = __halves2bfloat162(h2, h3);
        lo[2 * i + 0] = __halves2bfloat162(l0, l1);
        lo[2 * i + 1] = __halves2bfloat162(l2, l3);
    }
}

// ---------------------------------------------------------------------------
// Launch
// ---------------------------------------------------------------------------
extern "C" void kernel_launch(void* const* d_in, const int* in_sizes, int n_in,
                              void* d_out, int out_size) {
    const float* x   = (const float*)d_in[0];
    const int*   gwq = (const int*)  d_in[1];
    const float* gsc = (const float*)d_in[2];
    const int*   uwq = (const int*)  d_in[3];
    const float* usc = (const float*)d_in[4];
    const int*   dwq = (const int*)  d_in[5];
    const float* dsc = (const float*)d_in[6];
    float* out = (float*)d_out;

    cudaFuncSetAttribute(k_gemm_sk, cudaFuncAttributeMaxDynamicSharedMemorySize, SMEM_B);
    cudaFuncSetAttribute(k_gemm_gu, cudaFuncAttributeMaxDynamicSharedMemorySize, SMEM2);

    __nv_bfloat16 *wg, *wu, *wd, *xhi, *xlo, *hhi, *hlo;
    float *part;
    cudaGetSymbolAddress((void**)&wg,  g_wg);
    cudaGetSymbolAddress((void**)&wu,  g_wu);
    cudaGetSymbolAddress((void**)&wd,  g_wd);
    cudaGetSymbolAddress((void**)&xhi, g_xhi);
    cudaGetSymbolAddress((void**)&xlo, g_xlo);
    cudaGetSymbolAddress((void**)&hhi, g_hhi);
    cudaGetSymbolAddress((void**)&hlo, g_hlo);
    cudaGetSymbolAddress((void**)&part, g_part);

    const int CT = 256;
    {
        int n4 = IDIM * HDIM / 4;
        k_convert_w<<<4096, CT>>>((const int4*)gwq, (uint2*)wg, n4);
        k_convert_w<<<4096, CT>>>((const int4*)uwq, (uint2*)wu, n4);
        k_convert_w<<<4096, CT>>>((const int4*)dwq, (uint2*)wd, n4);
    }
    k_split_x<<<4096, CT>>>((const float4*)x, (__nv_bfloat162*)xhi,
                            (__nv_bfloat162*)xlo, MDIM * HDIM / 4);

    dim3 grid1(MDIM / 128, IDIM / 128);   // (32, 112), m fastest for W-slab L2 reuse
    k_gemm_gu<<<grid1, THREADS, SMEM2>>>(xhi, xlo, wg, wu, gsc, usc, hhi, hlo, HDIM);

    dim3 grid2(MDIM / BM, HDIM / BN, 2);  // (32, 16, 2) split-K
    k_gemm_sk<<<grid2, THREADS, SMEM_B>>>(hhi, hlo, wd, dsc, part,
                                          HDIM, IDIM, IDIM / 2);

    k_add<<<2048, CT>>>((const float4*)part,
                        (const float4*)(part + (size_t)MDIM * HDIM),
                        (float4*)out, MDIM * HDIM / 4);
}

// round 15
// speedup vs baseline: 1.1375x; 1.0075x over previous
#include <cuda_runtime.h>
#include <cuda_bf16.h>
#include <cstdint>

// ---------------------------------------------------------------------------
// MistralQuantizedMLP via bf16 hi/lo split GEMMs on legacy HMMA
// (mma.sync.m16n8k16.bf16) — only fast tensor path from compute_103 PTX.
//
// R15 = R9 GEMM structure (validated 7049us) + single merged prep kernel
// (3 weight converts + x split run concurrently, one launch) + hoisted
// epilogue scale loads.
//   gu: fused gate+up GEMM, CTA 128x(128 pair), warp 64x(32 pair),
//       SwiGLU + hi/lo split epilogue.
//   down: split-K=2, fp32 partial buffers + k_add combine.
// ---------------------------------------------------------------------------

static constexpr int MDIM = 4096, HDIM = 4096, IDIM = 14336;
static constexpr int THREADS = 256;
static constexpr int PITCH = 144;               // 128B row + 16B pad

// ---- down-GEMM geometry: CTA 128x256, warp 64x64 ----
static constexpr int BM = 128, BN = 256, BK = 64;
static constexpr int MAT_A = BM * PITCH;            // 18432
static constexpr int MAT_B = BN * PITCH;            // 36864
static constexpr int STAGE_B = 2 * MAT_A + MAT_B;   // 73728
static constexpr int STAGES = 3;
static constexpr int SMEM_B = STAGES * STAGE_B;     // 221184

// ---- fused gate/up geometry: CTA 128x(128 pair), warp 64x(32 pair) ----
static constexpr int MAT2 = 128 * PITCH;            // 18432
static constexpr int STAGE2 = 4 * MAT2;             // A0,A1,Bg,Bu = 73728
static constexpr int SMEM2 = STAGES * STAGE2;       // 221184

// ---- static device scratch (allocation-free rule) ----
__device__ __align__(1024) __nv_bfloat16 g_wg[(size_t)IDIM * HDIM];
__device__ __align__(1024) __nv_bfloat16 g_wu[(size_t)IDIM * HDIM];
__device__ __align__(1024) __nv_bfloat16 g_wd[(size_t)HDIM * IDIM];
__device__ __align__(1024) __nv_bfloat16 g_xhi[(size_t)MDIM * HDIM];
__device__ __align__(1024) __nv_bfloat16 g_xlo[(size_t)MDIM * HDIM];
__device__ __align__(1024) __nv_bfloat16 g_hhi[(size_t)MDIM * IDIM];
__device__ __align__(1024) __nv_bfloat16 g_hlo[(size_t)MDIM * IDIM];
__device__ __align__(1024) float         g_part[2 * (size_t)MDIM * HDIM];

// ---------------------------------------------------------------------------
// PTX helpers
// ---------------------------------------------------------------------------
__device__ __forceinline__ void cp_async16(void* sdst, const void* gsrc) {
    uint32_t s = (uint32_t)__cvta_generic_to_shared(sdst);
    asm volatile("cp.async.cg.shared.global [%0], [%1], 16;" :: "r"(s), "l"(gsrc));
}
__device__ __forceinline__ void ldm_x4(uint32_t* a, uint32_t addr) {
    asm volatile("ldmatrix.sync.aligned.m8n8.x4.shared.b16 {%0,%1,%2,%3}, [%4];"
                 : "=r"(a[0]), "=r"(a[1]), "=r"(a[2]), "=r"(a[3]) : "r"(addr));
}
__device__ __forceinline__ void mma16816(float* c, const uint32_t* a, const uint32_t* b) {
    asm volatile("mma.sync.aligned.m16n8k16.row.col.f32.bf16.bf16.f32 "
                 "{%0,%1,%2,%3}, {%4,%5,%6,%7}, {%8,%9}, {%0,%1,%2,%3};"
                 : "+f"(c[0]), "+f"(c[1]), "+f"(c[2]), "+f"(c[3])
                 : "r"(a[0]), "r"(a[1]), "r"(a[2]), "r"(a[3]), "r"(b[0]), "r"(b[1]));
}
__device__ __forceinline__ void split1(float v, __nv_bfloat16& h, __nv_bfloat16& l) {
    h = __float2bfloat16_rn(v);
    l = __float2bfloat16_rn(v - __bfloat162float(h));
}
__device__ __forceinline__ float silu_f(float g) { return g / (1.0f + expf(-g)); }

// ---------------------------------------------------------------------------
// Fused gate+up GEMM + SwiGLU + hi/lo split epilogue (R8/R9, proven).
// CTA: M=128, N=128 (both matrices). Warp: 64 x 32 pair. 8 warps.
// ---------------------------------------------------------------------------
__global__ __launch_bounds__(THREADS, 1)
void k_gemm_gu(const __nv_bfloat16* __restrict__ Ahi,
               const __nv_bfloat16* __restrict__ Alo,
               const __nv_bfloat16* __restrict__ Bg,
               const __nv_bfloat16* __restrict__ Bu,
               const float* __restrict__ gs, const float* __restrict__ us,
               __nv_bfloat16* __restrict__ Hhi, __nv_bfloat16* __restrict__ Hlo,
               int K) {
    extern __shared__ __align__(128) int8_t sm[];
    const int tid = threadIdx.x, lane = tid & 31, wid = tid >> 5;
    const int wm = wid >> 2, wn = wid & 3;
    const size_t bm = (size_t)blockIdx.x * 128;
    const size_t bn = (size_t)blockIdx.y * 128;

    const __nv_bfloat16* gA0 = Ahi + bm * K;
    const __nv_bfloat16* gA1 = Alo + bm * K;
    const __nv_bfloat16* gBg = Bg + bn * K;
    const __nv_bfloat16* gBu = Bu + bn * K;

    float accg[4][4][4], accu[4][4][4];
    #pragma unroll
    for (int i = 0; i < 4; i++)
        #pragma unroll
        for (int j = 0; j < 4; j++)
            #pragma unroll
            for (int r = 0; r < 4; r++) { accg[i][j][r] = 0.f; accu[i][j][r] = 0.f; }

    auto load_stage = [&](int s, int k0) {
        int8_t* base = sm + s * STAGE2;
        #pragma unroll
        for (int i = 0; i < 4; i++) {
            int c = tid + i * THREADS, row = c >> 3, ch = c & 7;
            cp_async16(base + row * PITCH + ch * 16, gA0 + (size_t)row * K + k0 + ch * 8);
        }
        #pragma unroll
        for (int i = 0; i < 4; i++) {
            int c = tid + i * THREADS, row = c >> 3, ch = c & 7;
            cp_async16(base + MAT2 + row * PITCH + ch * 16,
                       gA1 + (size_t)row * K + k0 + ch * 8);
        }
        #pragma unroll
        for (int i = 0; i < 4; i++) {
            int c = tid + i * THREADS, row = c >> 3, ch = c & 7;
            cp_async16(base + 2 * MAT2 + row * PITCH + ch * 16,
                       gBg + (size_t)row * K + k0 + ch * 8);
        }
        #pragma unroll
        for (int i = 0; i < 4; i++) {
            int c = tid + i * THREADS, row = c >> 3, ch = c & 7;
            cp_async16(base + 3 * MAT2 + row * PITCH + ch * 16,
                       gBu + (size_t)row * K + k0 + ch * 8);
        }
        asm volatile("cp.async.commit_group;" ::: "memory");
    };

    const int KT = K / BK;
    load_stage(0, 0);
    load_stage(1, BK);

    const uint32_t smb = (uint32_t)__cvta_generic_to_shared(sm);
    const uint32_t a_off = (uint32_t)((lane & 15) * PITCH + (lane >> 4) * 16);
    const uint32_t b_off = (uint32_t)((lane & 7) * PITCH +
                                      ((lane >> 3) & 1) * 16 +
                                      (lane >> 4) * 8 * PITCH);

    int stage = 0;
    for (int kt = 0; kt < KT; kt++) {
        asm volatile("cp.async.wait_group 1;" ::: "memory");
        __syncthreads();
        if (kt + 2 < KT) {
            int s2 = stage + 2; if (s2 >= STAGES) s2 -= STAGES;
            load_stage(s2, (kt + 2) * BK);
        } else {
            asm volatile("cp.async.commit_group;" ::: "memory");
        }

        const uint32_t st  = smb + (uint32_t)(stage * STAGE2);
        const uint32_t sA0 = st + (uint32_t)((wm * 64) * PITCH);
        const uint32_t sA1 = sA0 + (uint32_t)MAT2;
        const uint32_t sBg = st + 2u * MAT2 + (uint32_t)((wn * 32) * PITCH);
        const uint32_t sBu = st + 3u * MAT2 + (uint32_t)((wn * 32) * PITCH);

        #pragma unroll
        for (int ks = 0; ks < 4; ks++) {
            const uint32_t kb = (uint32_t)(ks * 32);
            uint32_t bg[4][2], bu[4][2];
            #pragma unroll
            for (int np = 0; np < 2; np++) {
                uint32_t t4[4];
                ldm_x4(t4, sBg + (uint32_t)(np * 16 * PITCH) + b_off + kb);
                bg[2*np][0] = t4[0]; bg[2*np][1] = t4[1];
                bg[2*np+1][0] = t4[2]; bg[2*np+1][1] = t4[3];
                ldm_x4(t4, sBu + (uint32_t)(np * 16 * PITCH) + b_off + kb);
                bu[2*np][0] = t4[0]; bu[2*np][1] = t4[1];
                bu[2*np+1][0] = t4[2]; bu[2*np+1][1] = t4[3];
            }
            uint32_t af[4][4];
            #pragma unroll
            for (int mi = 0; mi < 4; mi++)
                ldm_x4(af[mi], sA0 + (uint32_t)(mi * 16 * PITCH) + a_off + kb);
            #pragma unroll
            for (int mi = 0; mi < 4; mi++)
                #pragma unroll
                for (int ni = 0; ni < 4; ni++) {
                    mma16816(accg[mi][ni], af[mi], bg[ni]);
                    mma16816(accu[mi][ni], af[mi], bu[ni]);
                }
            #pragma unroll
            for (int mi = 0; mi < 4; mi++)
                ldm_x4(af[mi], sA1 + (uint32_t)(mi * 16 * PITCH) + a_off + kb);
            #pragma unroll
            for (int mi = 0; mi < 4; mi++)
                #pragma unroll
                for (int ni = 0; ni < 4; ni++) {
                    mma16816(accg[mi][ni], af[mi], bg[ni]);
                    mma16816(accu[mi][ni], af[mi], bu[ni]);
                }
        }
        if (++stage == STAGES) stage = 0;
    }

    // epilogue: hoisted per-channel scales -> SwiGLU -> hi/lo split -> store
    const int r0b = (int)bm + wm * 64;
    const int c0b = (int)bn + wn * 32;
    float gsc0[4], gsc1[4], usc0[4], usc1[4];
    #pragma unroll
    for (int ni = 0; ni < 4; ni++) {
        const int c0 = c0b + ni * 8 + (lane & 3) * 2;
        gsc0[ni] = __ldg(gs + c0); gsc1[ni] = __ldg(gs + c0 + 1);
        usc0[ni] = __ldg(us + c0); usc1[ni] = __ldg(us + c0 + 1);
    }
    #pragma unroll
    for (int mi = 0; mi < 4; mi++) {
        const int r0 = r0b + mi * 16 + (lane >> 2);
        #pragma unroll
        for (int ni = 0; ni < 4; ni++) {
            const int c0 = c0b + ni * 8 + (lane & 3) * 2;
            float h00 = silu_f(accg[mi][ni][0] * gsc0[ni]) * (accu[mi][ni][0] * usc0[ni]);
            float h01 = silu_f(accg[mi][ni][1] * gsc1[ni]) * (accu[mi][ni][1] * usc1[ni]);
            float h10 = silu_f(accg[mi][ni][2] * gsc0[ni]) * (accu[mi][ni][2] * usc0[ni]);
            float h11 = silu_f(accg[mi][ni][3] * gsc1[ni]) * (accu[mi][ni][3] * usc1[ni]);
            __nv_bfloat16 a0, b0, a1, b1, a2, b2, a3, b3;
            split1(h00, a0, b0); split1(h01, a1, b1);
            split1(h10, a2, b2); split1(h11, a3, b3);
            *reinterpret_cast<__nv_bfloat162*>(Hhi + (size_t)r0 * IDIM + c0) =
                __halves2bfloat162(a0, a1);
            *reinterpret_cast<__nv_bfloat162*>(Hlo + (size_t)r0 * IDIM + c0) =
                __halves2bfloat162(b0, b1);
            *reinterpret_cast<__nv_bfloat162*>(Hhi + (size_t)(r0 + 8) * IDIM + c0) =
                __halves2bfloat162(a2, a3);
            *reinterpret_cast<__nv_bfloat162*>(Hlo + (size_t)(r0 + 8) * IDIM + c0) =
                __halves2bfloat162(b2, b3);
        }
    }
}

// ---------------------------------------------------------------------------
// Down GEMM, split-K=2 (R9, proven): partial C per z-slice.
// ---------------------------------------------------------------------------
__global__ __launch_bounds__(THREADS, 1)
void k_gemm_sk(const __nv_bfloat16* __restrict__ Ahi,
               const __nv_bfloat16* __restrict__ Alo,
               const __nv_bfloat16* __restrict__ Bw,
               const float* __restrict__ scale,
               float* __restrict__ Cpart, int N, int Kld, int Kloc) {
    extern __shared__ __align__(128) int8_t sm[];
    const int tid = threadIdx.x, lane = tid & 31, wid = tid >> 5;
    const int wm = wid >> 2, wn = wid & 3;
    const size_t bm = (size_t)blockIdx.x * BM;
    const size_t bn = (size_t)blockIdx.y * BN;
    const int k0g = blockIdx.z * Kloc;

    const __nv_bfloat16* gA0 = Ahi + bm * Kld + k0g;
    const __nv_bfloat16* gA1 = Alo + bm * Kld + k0g;
    const __nv_bfloat16* gB  = Bw  + bn * Kld + k0g;
    float* C = Cpart + (size_t)blockIdx.z * MDIM * HDIM;

    float acc[4][8][4];
    #pragma unroll
    for (int i = 0; i < 4; i++)
        #pragma unroll
        for (int j = 0; j < 8; j++)
            #pragma unroll
            for (int r = 0; r < 4; r++) acc[i][j][r] = 0.0f;

    auto load_stage = [&](int s, int k0) {
        int8_t* base = sm + s * STAGE_B;
        #pragma unroll
        for (int i = 0; i < 4; i++) {
            int c = tid + i * THREADS, row = c >> 3, ch = c & 7;
            cp_async16(base + row * PITCH + ch * 16,
                       gA0 + (size_t)row * Kld + k0 + ch * 8);
        }
        #pragma unroll
        for (int i = 0; i < 4; i++) {
            int c = tid + i * THREADS, row = c >> 3, ch = c & 7;
            cp_async16(base + MAT_A + row * PITCH + ch * 16,
                       gA1 + (size_t)row * Kld + k0 + ch * 8);
        }
        #pragma unroll
        for (int i = 0; i < 8; i++) {
            int c = tid + i * THREADS, row = c >> 3, ch = c & 7;
            cp_async16(base + 2 * MAT_A + row * PITCH + ch * 16,
                       gB + (size_t)row * Kld + k0 + ch * 8);
        }
        asm volatile("cp.async.commit_group;" ::: "memory");
    };

    const int KT = Kloc / BK;
    load_stage(0, 0);
    load_stage(1, BK);

    const uint32_t smb = (uint32_t)__cvta_generic_to_shared(sm);
    const uint32_t a_off = (uint32_t)((lane & 15) * PITCH + (lane >> 4) * 16);
    const uint32_t b_off = (uint32_t)((lane & 7) * PITCH +
                                      ((lane >> 3) & 1) * 16 +
                                      (lane >> 4) * 8 * PITCH);

    int stage = 0;
    for (int kt = 0; kt < KT; kt++) {
        asm volatile("cp.async.wait_group 1;" ::: "memory");
        __syncthreads();
        if (kt + 2 < KT) {
            int s2 = stage + 2; if (s2 >= STAGES) s2 -= STAGES;
            load_stage(s2, (kt + 2) * BK);
        } else {
            asm volatile("cp.async.commit_group;" ::: "memory");
        }

        const uint32_t st  = smb + (uint32_t)(stage * STAGE_B);
        const uint32_t sA0 = st + (uint32_t)((wm * 64) * PITCH);
        const uint32_t sA1 = sA0 + (uint32_t)MAT_A;
        const uint32_t sB  = st + 2u * MAT_A + (uint32_t)((wn * 64) * PITCH);

        #pragma unroll
        for (int ks = 0; ks < 4; ks++) {
            const uint32_t kb = (uint32_t)(ks * 32);
            uint32_t bf[8][2];
            #pragma unroll
            for (int np = 0; np < 4; np++) {
                uint32_t t4[4];
                ldm_x4(t4, sB + (uint32_t)(np * 16 * PITCH) + b_off + kb);
                bf[2 * np][0] = t4[0]; bf[2 * np][1] = t4[1];
                bf[2 * np + 1][0] = t4[2]; bf[2 * np + 1][1] = t4[3];
            }
            uint32_t af[4][4];
            #pragma unroll
            for (int mi = 0; mi < 4; mi++)
                ldm_x4(af[mi], sA0 + (uint32_t)(mi * 16 * PITCH) + a_off + kb);
            #pragma unroll
            for (int mi = 0; mi < 4; mi++)
                #pragma unroll
                for (int ni = 0; ni < 8; ni++)
                    mma16816(acc[mi][ni], af[mi], bf[ni]);
            #pragma unroll
            for (int mi = 0; mi < 4; mi++)
                ldm_x4(af[mi], sA1 + (uint32_t)(mi * 16 * PITCH) + a_off + kb);
            #pragma unroll
            for (int mi = 0; mi < 4; mi++)
                #pragma unroll
                for (int ni = 0; ni < 8; ni++)
                    mma16816(acc[mi][ni], af[mi], bf[ni]);
        }
        if (++stage == STAGES) stage = 0;
    }

    const int r0b = (int)bm + wm * 64;
    const int c0b = (int)bn + wn * 64;
    #pragma unroll
    for (int mi = 0; mi < 4; mi++) {
        const int r0 = r0b + mi * 16 + (lane >> 2);
        #pragma unroll
        for (int ni = 0; ni < 8; ni++) {
            const int c0 = c0b + ni * 8 + (lane & 3) * 2;
            const float s0 = __ldg(scale + c0), s1 = __ldg(scale + c0 + 1);
            float2 v0 = make_float2(acc[mi][ni][0] * s0, acc[mi][ni][1] * s1);
            float2 v1 = make_float2(acc[mi][ni][2] * s0, acc[mi][ni][3] * s1);
            *reinterpret_cast<float2*>(C + (size_t)r0 * N + c0) = v0;
            *reinterpret_cast<float2*>(C + (size_t)(r0 + 8) * N + c0) = v1;
        }
    }
}

// combine the two split-K partials
__global__ void k_add(const float4* __restrict__ p0, const float4* __restrict__ p1,
                      float4* __restrict__ out, int n4) {
    int i = blockIdx.x * blockDim.x + threadIdx.x;
    int stride = gridDim.x * blockDim.x;
    for (; i < n4; i += stride) {
        float4 a = p0[i], b = p1[i];
        out[i] = make_float4(a.x + b.x, a.y + b.y, a.z + b.z, a.w + b.w);
    }
}

// ---------------------------------------------------------------------------
// Merged prep: 3 weight converts + x hi/lo split in ONE launch.
// blockIdx.x >> 12 selects the job (4096 blocks each); jobs run concurrently
// so their load/store streams interleave across SMs (better MLP, one tail).
// ---------------------------------------------------------------------------
__global__ __launch_bounds__(256)
void k_prep(const int4* __restrict__ gwq, const int4* __restrict__ uwq,
            const int4* __restrict__ dwq, const float4* __restrict__ x,
            uint2* __restrict__ wg, uint2* __restrict__ wu,
            uint2* __restrict__ wd,
            __nv_bfloat162* __restrict__ xhi, __nv_bfloat162* __restrict__ xlo) {
    const int job = blockIdx.x >> 12;
    const int blk = blockIdx.x & 4095;
    const int stride = 4096 * 256;
    int i = blk * 256 + threadIdx.x;

    if (job < 3) {
        const int4* src = (job == 0) ? gwq : (job == 1) ? uwq : dwq;
        uint2* dst = (job == 0) ? wg : (job == 1) ? wu : wd;
        const int n4 = IDIM * HDIM / 4;
        for (; i < n4; i += stride) {
            int4 v = src[i];
            __nv_bfloat162 a0 = __halves2bfloat162(__float2bfloat16_rn((float)v.x),
                                                   __float2bfloat16_rn((float)v.y));
            __nv_bfloat162 a1 = __halves2bfloat162(__float2bfloat16_rn((float)v.z),
                                                   __float2bfloat16_rn((float)v.w));
            dst[i] = make_uint2(*reinterpret_cast<uint32_t*>(&a0),
                                *reinterpret_cast<uint32_t*>(&a1));
        }
    } else {
        const int n4 = MDIM * HDIM / 4;
        for (; i < n4; i += stride) {
            float4 v = x[i];
            __nv_bfloat16 h0, l0, h1, l1, h2, l2, h3, l3;
            split1(v.x, h0, l0); split1(v.y, h1, l1);
            split1(v.z, h2, l2); split1(v.w, h3, l3);
            xhi[2 * i + 0] = __halves2bfloat162(h0, h1);
            xhi[2 * i + 1] = __halves2bfloat162(h2, h3);
            xlo[2 * i + 0] = __halves2bfloat162(l0, l1);
            xlo[2 * i + 1] = __halves2bfloat162(l2, l3);
        }
    }
}

// ---------------------------------------------------------------------------
// Launch
// ---------------------------------------------------------------------------
extern "C" void kernel_launch(void* const* d_in, const int* in_sizes, int n_in,
                              void* d_out, int out_size) {
    const float* x   = (const float*)d_in[0];
    const int*   gwq = (const int*)  d_in[1];
    const float* gsc = (const float*)d_in[2];
    const int*   uwq = (const int*)  d_in[3];
    const float* usc = (const float*)d_in[4];
    const int*   dwq = (const int*)  d_in[5];
    const float* dsc = (const float*)d_in[6];
    float* out = (float*)d_out;

    cudaFuncSetAttribute(k_gemm_sk, cudaFuncAttributeMaxDynamicSharedMemorySize, SMEM_B);
    cudaFuncSetAttribute(k_gemm_gu, cudaFuncAttributeMaxDynamicSharedMemorySize, SMEM2);

    __nv_bfloat16 *wg, *wu, *wd, *xhi, *xlo, *hhi, *hlo;
    float *part;
    cudaGetSymbolAddress((void**)&wg,  g_wg);
    cudaGetSymbolAddress((void**)&wu,  g_wu);
    cudaGetSymbolAddress((void**)&wd,  g_wd);
    cudaGetSymbolAddress((void**)&xhi, g_xhi);
    cudaGetSymbolAddress((void**)&xlo, g_xlo);
    cudaGetSymbolAddress((void**)&hhi, g_hhi);
    cudaGetSymbolAddress((void**)&hlo, g_hlo);
    cudaGetSymbolAddress((void**)&part, g_part);

    k_prep<<<4 * 4096, 256>>>((const int4*)gwq, (const int4*)uwq,
                              (const int4*)dwq, (const float4*)x,
                              (uint2*)wg, (uint2*)wu, (uint2*)wd,
                              (__nv_bfloat162*)xhi, (__nv_bfloat162*)xlo);

    dim3 grid1(MDIM / 128, IDIM / 128);   // (32, 112), m fastest for W-slab L2 reuse
    k_gemm_gu<<<grid1, THREADS, SMEM2>>>(xhi, xlo, wg, wu, gsc, usc, hhi, hlo, HDIM);

    dim3 grid2(MDIM / BM, HDIM / BN, 2);  // (32, 16, 2) split-K
    k_gemm_sk<<<grid2, THREADS, SMEM_B>>>(hhi, hlo, wd, dsc, part,
                                          HDIM, IDIM, IDIM / 2);

    k_add<<<2048, 256>>>((const float4*)part,
                         (const float4*)(part + (size_t)MDIM * HDIM),
                         (float4*)out, MDIM * HDIM / 4);
}

// round 16
// speedup vs baseline: 1.3197x; 1.1602x over previous
#include <cuda_runtime.h>
#include <cuda_bf16.h>
#include <cuda_fp16.h>
#include <cstdint>

// ---------------------------------------------------------------------------
// MistralQuantizedMLP via HMMA (mma.sync m16n8k16) — only fast tensor path
// from compute_103 PTX.
//
// R16 = R15 + single-pass fp16 down-GEMM:
//   gu: bf16 hi/lo x, fused gate+up GEMM, SwiGLU epilogue -> h stored fp16.
//   down: h(fp16) @ Wd(fp16, exact) single pass, split-K=2 + k_add.
//   Error model: fp16 h rounding ~2.8e-4 L2-rel (threshold 1e-3).
// ---------------------------------------------------------------------------

static constexpr int MDIM = 4096, HDIM = 4096, IDIM = 14336;
static constexpr int THREADS = 256;
static constexpr int PITCH = 144;               // 128B row + 16B pad

// ---- down-GEMM geometry: CTA 128x256, warp 64x64, single A ----
static constexpr int BM = 128, BN = 256, BK = 64;
static constexpr int MAT_A = BM * PITCH;            // 18432
static constexpr int MAT_B = BN * PITCH;            // 36864
static constexpr int STAGE_B = MAT_A + MAT_B;       // 55296
static constexpr int STAGES = 3;
static constexpr int SMEM_B = STAGES * STAGE_B;     // 165888

// ---- fused gate/up geometry: CTA 128x(128 pair), warp 64x(32 pair) ----
static constexpr int MAT2 = 128 * PITCH;            // 18432
static constexpr int STAGE2 = 4 * MAT2;             // A0,A1,Bg,Bu = 73728
static constexpr int SMEM2 = STAGES * STAGE2;       // 221184

// ---- static device scratch (allocation-free rule) ----
__device__ __align__(1024) __nv_bfloat16 g_wg[(size_t)IDIM * HDIM];
__device__ __align__(1024) __nv_bfloat16 g_wu[(size_t)IDIM * HDIM];
__device__ __align__(1024) __half        g_wd[(size_t)HDIM * IDIM];
__device__ __align__(1024) __nv_bfloat16 g_xhi[(size_t)MDIM * HDIM];
__device__ __align__(1024) __nv_bfloat16 g_xlo[(size_t)MDIM * HDIM];
__device__ __align__(1024) __half        g_hh[(size_t)MDIM * IDIM];
__device__ __align__(1024) float         g_part[2 * (size_t)MDIM * HDIM];

// ---------------------------------------------------------------------------
// PTX helpers
// ---------------------------------------------------------------------------
__device__ __forceinline__ void cp_async16(void* sdst, const void* gsrc) {
    uint32_t s = (uint32_t)__cvta_generic_to_shared(sdst);
    asm volatile("cp.async.cg.shared.global [%0], [%1], 16;" :: "r"(s), "l"(gsrc));
}
__device__ __forceinline__ void ldm_x4(uint32_t* a, uint32_t addr) {
    asm volatile("ldmatrix.sync.aligned.m8n8.x4.shared.b16 {%0,%1,%2,%3}, [%4];"
                 : "=r"(a[0]), "=r"(a[1]), "=r"(a[2]), "=r"(a[3]) : "r"(addr));
}
__device__ __forceinline__ void mma16816(float* c, const uint32_t* a, const uint32_t* b) {
    asm volatile("mma.sync.aligned.m16n8k16.row.col.f32.bf16.bf16.f32 "
                 "{%0,%1,%2,%3}, {%4,%5,%6,%7}, {%8,%9}, {%0,%1,%2,%3};"
                 : "+f"(c[0]), "+f"(c[1]), "+f"(c[2]), "+f"(c[3])
                 : "r"(a[0]), "r"(a[1]), "r"(a[2]), "r"(a[3]), "r"(b[0]), "r"(b[1]));
}
__device__ __forceinline__ void mma16816h(float* c, const uint32_t* a, const uint32_t* b) {
    asm volatile("mma.sync.aligned.m16n8k16.row.col.f32.f16.f16.f32 "
                 "{%0,%1,%2,%3}, {%4,%5,%6,%7}, {%8,%9}, {%0,%1,%2,%3};"
                 : "+f"(c[0]), "+f"(c[1]), "+f"(c[2]), "+f"(c[3])
                 : "r"(a[0]), "r"(a[1]), "r"(a[2]), "r"(a[3]), "r"(b[0]), "r"(b[1]));
}
__device__ __forceinline__ void split1(float v, __nv_bfloat16& h, __nv_bfloat16& l) {
    h = __float2bfloat16_rn(v);
    l = __float2bfloat16_rn(v - __bfloat162float(h));
}
__device__ __forceinline__ float silu_f(float g) { return g / (1.0f + expf(-g)); }

// ---------------------------------------------------------------------------
// Fused gate+up GEMM + SwiGLU epilogue -> fp16 h.
// CTA: M=128, N=128 (both matrices). Warp: 64 x 32 pair. 8 warps.
// ---------------------------------------------------------------------------
__global__ __launch_bounds__(THREADS, 1)
void k_gemm_gu(const __nv_bfloat16* __restrict__ Ahi,
               const __nv_bfloat16* __restrict__ Alo,
               const __nv_bfloat16* __restrict__ Bg,
               const __nv_bfloat16* __restrict__ Bu,
               const float* __restrict__ gs, const float* __restrict__ us,
               __half* __restrict__ Hh, int K) {
    extern __shared__ __align__(128) int8_t sm[];
    const int tid = threadIdx.x, lane = tid & 31, wid = tid >> 5;
    const int wm = wid >> 2, wn = wid & 3;
    const size_t bm = (size_t)blockIdx.x * 128;
    const size_t bn = (size_t)blockIdx.y * 128;

    const __nv_bfloat16* gA0 = Ahi + bm * K;
    const __nv_bfloat16* gA1 = Alo + bm * K;
    const __nv_bfloat16* gBg = Bg + bn * K;
    const __nv_bfloat16* gBu = Bu + bn * K;

    float accg[4][4][4], accu[4][4][4];
    #pragma unroll
    for (int i = 0; i < 4; i++)
        #pragma unroll
        for (int j = 0; j < 4; j++)
            #pragma unroll
            for (int r = 0; r < 4; r++) { accg[i][j][r] = 0.f; accu[i][j][r] = 0.f; }

    auto load_stage = [&](int s, int k0) {
        int8_t* base = sm + s * STAGE2;
        #pragma unroll
        for (int i = 0; i < 4; i++) {
            int c = tid + i * THREADS, row = c >> 3, ch = c & 7;
            cp_async16(base + row * PITCH + ch * 16, gA0 + (size_t)row * K + k0 + ch * 8);
        }
        #pragma unroll
        for (int i = 0; i < 4; i++) {
            int c = tid + i * THREADS, row = c >> 3, ch = c & 7;
            cp_async16(base + MAT2 + row * PITCH + ch * 16,
                       gA1 + (size_t)row * K + k0 + ch * 8);
        }
        #pragma unroll
        for (int i = 0; i < 4; i++) {
            int c = tid + i * THREADS, row = c >> 3, ch = c & 7;
            cp_async16(base + 2 * MAT2 + row * PITCH + ch * 16,
                       gBg + (size_t)row * K + k0 + ch * 8);
        }
        #pragma unroll
        for (int i = 0; i < 4; i++) {
            int c = tid + i * THREADS, row = c >> 3, ch = c & 7;
            cp_async16(base + 3 * MAT2 + row * PITCH + ch * 16,
                       gBu + (size_t)row * K + k0 + ch * 8);
        }
        asm volatile("cp.async.commit_group;" ::: "memory");
    };

    const int KT = K / BK;
    load_stage(0, 0);
    load_stage(1, BK);

    const uint32_t smb = (uint32_t)__cvta_generic_to_shared(sm);
    const uint32_t a_off = (uint32_t)((lane & 15) * PITCH + (lane >> 4) * 16);
    const uint32_t b_off = (uint32_t)((lane & 7) * PITCH +
                                      ((lane >> 3) & 1) * 16 +
                                      (lane >> 4) * 8 * PITCH);

    int stage = 0;
    for (int kt = 0; kt < KT; kt++) {
        asm volatile("cp.async.wait_group 1;" ::: "memory");
        __syncthreads();
        if (kt + 2 < KT) {
            int s2 = stage + 2; if (s2 >= STAGES) s2 -= STAGES;
            load_stage(s2, (kt + 2) * BK);
        } else {
            asm volatile("cp.async.commit_group;" ::: "memory");
        }

        const uint32_t st  = smb + (uint32_t)(stage * STAGE2);
        const uint32_t sA0 = st + (uint32_t)((wm * 64) * PITCH);
        const uint32_t sA1 = sA0 + (uint32_t)MAT2;
        const uint32_t sBg = st + 2u * MAT2 + (uint32_t)((wn * 32) * PITCH);
        const uint32_t sBu = st + 3u * MAT2 + (uint32_t)((wn * 32) * PITCH);

        #pragma unroll
        for (int ks = 0; ks < 4; ks++) {
            const uint32_t kb = (uint32_t)(ks * 32);
            uint32_t bg[4][2], bu[4][2];
            #pragma unroll
            for (int np = 0; np < 2; np++) {
                uint32_t t4[4];
                ldm_x4(t4, sBg + (uint32_t)(np * 16 * PITCH) + b_off + kb);
                bg[2*np][0] = t4[0]; bg[2*np][1] = t4[1];
                bg[2*np+1][0] = t4[2]; bg[2*np+1][1] = t4[3];
                ldm_x4(t4, sBu + (uint32_t)(np * 16 * PITCH) + b_off + kb);
                bu[2*np][0] = t4[0]; bu[2*np][1] = t4[1];
                bu[2*np+1][0] = t4[2]; bu[2*np+1][1] = t4[3];
            }
            uint32_t af[4][4];
            #pragma unroll
            for (int mi = 0; mi < 4; mi++)
                ldm_x4(af[mi], sA0 + (uint32_t)(mi * 16 * PITCH) + a_off + kb);
            #pragma unroll
            for (int mi = 0; mi < 4; mi++)
                #pragma unroll
                for (int ni = 0; ni < 4; ni++) {
                    mma16816(accg[mi][ni], af[mi], bg[ni]);
                    mma16816(accu[mi][ni], af[mi], bu[ni]);
                }
            #pragma unroll
            for (int mi = 0; mi < 4; mi++)
                ldm_x4(af[mi], sA1 + (uint32_t)(mi * 16 * PITCH) + a_off + kb);
            #pragma unroll
            for (int mi = 0; mi < 4; mi++)
                #pragma unroll
                for (int ni = 0; ni < 4; ni++) {
                    mma16816(accg[mi][ni], af[mi], bg[ni]);
                    mma16816(accu[mi][ni], af[mi], bu[ni]);
                }
        }
        if (++stage == STAGES) stage = 0;
    }

    // epilogue: hoisted scales -> SwiGLU -> fp16 h store
    const int r0b = (int)bm + wm * 64;
    const int c0b = (int)bn + wn * 32;
    float gsc0[4], gsc1[4], usc0[4], usc1[4];
    #pragma unroll
    for (int ni = 0; ni < 4; ni++) {
        const int c0 = c0b + ni * 8 + (lane & 3) * 2;
        gsc0[ni] = __ldg(gs + c0); gsc1[ni] = __ldg(gs + c0 + 1);
        usc0[ni] = __ldg(us + c0); usc1[ni] = __ldg(us + c0 + 1);
    }
    #pragma unroll
    for (int mi = 0; mi < 4; mi++) {
        const int r0 = r0b + mi * 16 + (lane >> 2);
        #pragma unroll
        for (int ni = 0; ni < 4; ni++) {
            const int c0 = c0b + ni * 8 + (lane & 3) * 2;
            float h00 = silu_f(accg[mi][ni][0] * gsc0[ni]) * (accu[mi][ni][0] * usc0[ni]);
            float h01 = silu_f(accg[mi][ni][1] * gsc1[ni]) * (accu[mi][ni][1] * usc1[ni]);
            float h10 = silu_f(accg[mi][ni][2] * gsc0[ni]) * (accu[mi][ni][2] * usc0[ni]);
            float h11 = silu_f(accg[mi][ni][3] * gsc1[ni]) * (accu[mi][ni][3] * usc1[ni]);
            *reinterpret_cast<__half2*>(Hh + (size_t)r0 * IDIM + c0) =
                __halves2half2(__float2half_rn(h00), __float2half_rn(h01));
            *reinterpret_cast<__half2*>(Hh + (size_t)(r0 + 8) * IDIM + c0) =
                __halves2half2(__float2half_rn(h10), __float2half_rn(h11));
        }
    }
}

// ---------------------------------------------------------------------------
// Down GEMM, fp16 single-pass, split-K=2: partial C per z-slice.
// ---------------------------------------------------------------------------
__global__ __launch_bounds__(THREADS, 1)
void k_gemm_sk(const __half* __restrict__ Ah,
               const __half* __restrict__ Bw,
               const float* __restrict__ scale,
               float* __restrict__ Cpart, int N, int Kld, int Kloc) {
    extern __shared__ __align__(128) int8_t sm[];
    const int tid = threadIdx.x, lane = tid & 31, wid = tid >> 5;
    const int wm = wid >> 2, wn = wid & 3;
    const size_t bm = (size_t)blockIdx.x * BM;
    const size_t bn = (size_t)blockIdx.y * BN;
    const int k0g = blockIdx.z * Kloc;

    const __half* gA = Ah + bm * Kld + k0g;
    const __half* gB = Bw + bn * Kld + k0g;
    float* C = Cpart + (size_t)blockIdx.z * MDIM * HDIM;

    float acc[4][8][4];
    #pragma unroll
    for (int i = 0; i < 4; i++)
        #pragma unroll
        for (int j = 0; j < 8; j++)
            #pragma unroll
            for (int r = 0; r < 4; r++) acc[i][j][r] = 0.0f;

    auto load_stage = [&](int s, int k0) {
        int8_t* base = sm + s * STAGE_B;
        #pragma unroll
        for (int i = 0; i < 4; i++) {
            int c = tid + i * THREADS, row = c >> 3, ch = c & 7;
            cp_async16(base + row * PITCH + ch * 16,
                       gA + (size_t)row * Kld + k0 + ch * 8);
        }
        #pragma unroll
        for (int i = 0; i < 8; i++) {
            int c = tid + i * THREADS, row = c >> 3, ch = c & 7;
            cp_async16(base + MAT_A + row * PITCH + ch * 16,
                       gB + (size_t)row * Kld + k0 + ch * 8);
        }
        asm volatile("cp.async.commit_group;" ::: "memory");
    };

    const int KT = Kloc / BK;
    load_stage(0, 0);
    load_stage(1, BK);

    const uint32_t smb = (uint32_t)__cvta_generic_to_shared(sm);
    const uint32_t a_off = (uint32_t)((lane & 15) * PITCH + (lane >> 4) * 16);
    const uint32_t b_off = (uint32_t)((lane & 7) * PITCH +
                                      ((lane >> 3) & 1) * 16 +
                                      (lane >> 4) * 8 * PITCH);

    int stage = 0;
    for (int kt = 0; kt < KT; kt++) {
        asm volatile("cp.async.wait_group 1;" ::: "memory");
        __syncthreads();
        if (kt + 2 < KT) {
            int s2 = stage + 2; if (s2 >= STAGES) s2 -= STAGES;
            load_stage(s2, (kt + 2) * BK);
        } else {
            asm volatile("cp.async.commit_group;" ::: "memory");
        }

        const uint32_t st  = smb + (uint32_t)(stage * STAGE_B);
        const uint32_t sA  = st + (uint32_t)((wm * 64) * PITCH);
        const uint32_t sB  = st + (uint32_t)MAT_A + (uint32_t)((wn * 64) * PITCH);

        #pragma unroll
        for (int ks = 0; ks < 4; ks++) {
            const uint32_t kb = (uint32_t)(ks * 32);
            uint32_t bf[8][2];
            #pragma unroll
            for (int np = 0; np < 4; np++) {
                uint32_t t4[4];
                ldm_x4(t4, sB + (uint32_t)(np * 16 * PITCH) + b_off + kb);
                bf[2 * np][0] = t4[0]; bf[2 * np][1] = t4[1];
                bf[2 * np + 1][0] = t4[2]; bf[2 * np + 1][1] = t4[3];
            }
            uint32_t af[4][4];
            #pragma unroll
            for (int mi = 0; mi < 4; mi++)
                ldm_x4(af[mi], sA + (uint32_t)(mi * 16 * PITCH) + a_off + kb);
            #pragma unroll
            for (int mi = 0; mi < 4; mi++)
                #pragma unroll
                for (int ni = 0; ni < 8; ni++)
                    mma16816h(acc[mi][ni], af[mi], bf[ni]);
        }
        if (++stage == STAGES) stage = 0;
    }

    const int r0b = (int)bm + wm * 64;
    const int c0b = (int)bn + wn * 64;
    #pragma unroll
    for (int mi = 0; mi < 4; mi++) {
        const int r0 = r0b + mi * 16 + (lane >> 2);
        #pragma unroll
        for (int ni = 0; ni < 8; ni++) {
            const int c0 = c0b + ni * 8 + (lane & 3) * 2;
            const float s0 = __ldg(scale + c0), s1 = __ldg(scale + c0 + 1);
            float2 v0 = make_float2(acc[mi][ni][0] * s0, acc[mi][ni][1] * s1);
            float2 v1 = make_float2(acc[mi][ni][2] * s0, acc[mi][ni][3] * s1);
            *reinterpret_cast<float2*>(C + (size_t)r0 * N + c0) = v0;
            *reinterpret_cast<float2*>(C + (size_t)(r0 + 8) * N + c0) = v1;
        }
    }
}

// combine the two split-K partials
__global__ void k_add(const float4* __restrict__ p0, const float4* __restrict__ p1,
                      float4* __restrict__ out, int n4) {
    int i = blockIdx.x * blockDim.x + threadIdx.x;
    int stride = gridDim.x * blockDim.x;
    for (; i < n4; i += stride) {
        float4 a = p0[i], b = p1[i];
        out[i] = make_float4(a.x + b.x, a.y + b.y, a.z + b.z, a.w + b.w);
    }
}

// ---------------------------------------------------------------------------
// Merged prep: gate/up -> bf16, down -> fp16 (exact), x hi/lo split.
// blockIdx.x >> 12 selects the job (4096 blocks each).
// ---------------------------------------------------------------------------
__global__ __launch_bounds__(256)
void k_prep(const int4* __restrict__ gwq, const int4* __restrict__ uwq,
            const int4* __restrict__ dwq, const float4* __restrict__ x,
            uint2* __restrict__ wg, uint2* __restrict__ wu,
            uint2* __restrict__ wd,
            __nv_bfloat162* __restrict__ xhi, __nv_bfloat162* __restrict__ xlo) {
    const int job = blockIdx.x >> 12;
    const int blk = blockIdx.x & 4095;
    const int stride = 4096 * 256;
    int i = blk * 256 + threadIdx.x;

    if (job < 2) {
        const int4* src = (job == 0) ? gwq : uwq;
        uint2* dst = (job == 0) ? wg : wu;
        const int n4 = IDIM * HDIM / 4;
        for (; i < n4; i += stride) {
            int4 v = src[i];
            __nv_bfloat162 a0 = __halves2bfloat162(__float2bfloat16_rn((float)v.x),
                                                   __float2bfloat16_rn((float)v.y));
            __nv_bfloat162 a1 = __halves2bfloat162(__float2bfloat16_rn((float)v.z),
                                                   __float2bfloat16_rn((float)v.w));
            dst[i] = make_uint2(*reinterpret_cast<uint32_t*>(&a0),
                                *reinterpret_cast<uint32_t*>(&a1));
        }
    } else if (job == 2) {
        const int n4 = IDIM * HDIM / 4;
        for (; i < n4; i += stride) {
            int4 v = dwq[i];
            __half2 a0 = __halves2half2(__float2half_rn((float)v.x),
                                        __float2half_rn((float)v.y));
            __half2 a1 = __halves2half2(__float2half_rn((float)v.z),
                                        __float2half_rn((float)v.w));
            wd[i] = make_uint2(*reinterpret_cast<uint32_t*>(&a0),
                               *reinterpret_cast<uint32_t*>(&a1));
        }
    } else {
        const int n4 = MDIM * HDIM / 4;
        for (; i < n4; i += stride) {
            float4 v = x[i];
            __nv_bfloat16 h0, l0, h1, l1, h2, l2, h3, l3;
            split1(v.x, h0, l0); split1(v.y, h1, l1);
            split1(v.z, h2, l2); split1(v.w, h3, l3);
            xhi[2 * i + 0] = __halves2bfloat162(h0, h1);
            xhi[2 * i + 1] = __halves2bfloat162(h2, h3);
            xlo[2 * i + 0] = __halves2bfloat162(l0, l1);
            xlo[2 * i + 1] = __halves2bfloat162(l2, l3);
        }
    }
}

// ---------------------------------------------------------------------------
// Launch
// ---------------------------------------------------------------------------
extern "C" void kernel_launch(void* const* d_in, const int* in_sizes, int n_in,
                              void* d_out, int out_size) {
    const float* x   = (const float*)d_in[0];
    const int*   gwq = (const int*)  d_in[1];
    const float* gsc = (const float*)d_in[2];
    const int*   uwq = (const int*)  d_in[3];
    const float* usc = (const float*)d_in[4];
    const int*   dwq = (const int*)  d_in[5];
    const float* dsc = (const float*)d_in[6];
    float* out = (float*)d_out;

    cudaFuncSetAttribute(k_gemm_sk, cudaFuncAttributeMaxDynamicSharedMemorySize, SMEM_B);
    cudaFuncSetAttribute(k_gemm_gu, cudaFuncAttributeMaxDynamicSharedMemorySize, SMEM2);

    __nv_bfloat16 *wg, *wu, *xhi, *xlo;
    __half *wd, *hh;
    float *part;
    cudaGetSymbolAddress((void**)&wg,  g_wg);
    cudaGetSymbolAddress((void**)&wu,  g_wu);
    cudaGetSymbolAddress((void**)&wd,  g_wd);
    cudaGetSymbolAddress((void**)&xhi, g_xhi);
    cudaGetSymbolAddress((void**)&xlo, g_xlo);
    cudaGetSymbolAddress((void**)&hh,  g_hh);
    cudaGetSymbolAddress((void**)&part, g_part);

    k_prep<<<4 * 4096, 256>>>((const int4*)gwq, (const int4*)uwq,
                              (const int4*)dwq, (const float4*)x,
                              (uint2*)wg, (uint2*)wu, (uint2*)wd,
                              (__nv_bfloat162*)xhi, (__nv_bfloat162*)xlo);

    dim3 grid1(MDIM / 128, IDIM / 128);   // (32, 112), m fastest for W-slab L2 reuse
    k_gemm_gu<<<grid1, THREADS, SMEM2>>>(xhi, xlo, wg, wu, gsc, usc, hh, HDIM);

    dim3 grid2(MDIM / BM, HDIM / BN, 2);  // (32, 16, 2) split-K
    k_gemm_sk<<<grid2, THREADS, SMEM_B>>>(hh, wd, dsc, part, HDIM, IDIM, IDIM / 2);

    k_add<<<2048, 256>>>((const float4*)part,
                         (const float4*)(part + (size_t)MDIM * HDIM),
                         (float4*)out, MDIM * HDIM / 4);
}

// round 17
// speedup vs baseline: 1.9145x; 1.4507x over previous
#include <cuda_runtime.h>
#include <cuda_fp16.h>
#include <cstdint>

// ---------------------------------------------------------------------------
// MistralQuantizedMLP via fp16 HMMA (mma.sync m16n8k16.f16) — only fast
// tensor path from compute_103 PTX.
//
// R17 = R16 + single-pass fp16 gate/up GEMM:
//   x -> fp16 (quant err ~2.1e-4, measured calibration from R16)
//   all weights -> fp16 (int8-valued => exact)
//   gu: x(fp16) @ {Wg,Wu}(fp16) single pass, SwiGLU epilogue -> h fp16.
//   down: h(fp16) @ Wd(fp16) single pass, split-K=2 + k_add.
//   Predicted total rel_err ~4e-4 (threshold 1e-3).
// ---------------------------------------------------------------------------

static constexpr int MDIM = 4096, HDIM = 4096, IDIM = 14336;
static constexpr int THREADS = 256;
static constexpr int PITCH = 144;               // 128B row + 16B pad

// ---- down-GEMM geometry: CTA 128x256, warp 64x64, single A ----
static constexpr int BM = 128, BN = 256, BK = 64;
static constexpr int MAT_A = BM * PITCH;            // 18432
static constexpr int MAT_B = BN * PITCH;            // 36864
static constexpr int STAGE_B = MAT_A + MAT_B;       // 55296
static constexpr int STAGES = 3;
static constexpr int SMEM_B = STAGES * STAGE_B;     // 165888

// ---- fused gate/up geometry: CTA 128x(128 pair), warp 64x(32 pair) ----
static constexpr int MAT2 = 128 * PITCH;            // 18432
static constexpr int STAGE2 = 3 * MAT2;             // A, Bg, Bu = 55296
static constexpr int SMEM2 = STAGES * STAGE2;       // 165888

// ---- static device scratch (allocation-free rule) ----
__device__ __align__(1024) __half g_wg[(size_t)IDIM * HDIM];
__device__ __align__(1024) __half g_wu[(size_t)IDIM * HDIM];
__device__ __align__(1024) __half g_wd[(size_t)HDIM * IDIM];
__device__ __align__(1024) __half g_xh[(size_t)MDIM * HDIM];
__device__ __align__(1024) __half g_hh[(size_t)MDIM * IDIM];
__device__ __align__(1024) float  g_part[2 * (size_t)MDIM * HDIM];

// ---------------------------------------------------------------------------
// PTX helpers
// ---------------------------------------------------------------------------
__device__ __forceinline__ void cp_async16(void* sdst, const void* gsrc) {
    uint32_t s = (uint32_t)__cvta_generic_to_shared(sdst);
    asm volatile("cp.async.cg.shared.global [%0], [%1], 16;" :: "r"(s), "l"(gsrc));
}
__device__ __forceinline__ void ldm_x4(uint32_t* a, uint32_t addr) {
    asm volatile("ldmatrix.sync.aligned.m8n8.x4.shared.b16 {%0,%1,%2,%3}, [%4];"
                 : "=r"(a[0]), "=r"(a[1]), "=r"(a[2]), "=r"(a[3]) : "r"(addr));
}
__device__ __forceinline__ void mma16816h(float* c, const uint32_t* a, const uint32_t* b) {
    asm volatile("mma.sync.aligned.m16n8k16.row.col.f32.f16.f16.f32 "
                 "{%0,%1,%2,%3}, {%4,%5,%6,%7}, {%8,%9}, {%0,%1,%2,%3};"
                 : "+f"(c[0]), "+f"(c[1]), "+f"(c[2]), "+f"(c[3])
                 : "r"(a[0]), "r"(a[1]), "r"(a[2]), "r"(a[3]), "r"(b[0]), "r"(b[1]));
}
__device__ __forceinline__ float silu_f(float g) { return g / (1.0f + expf(-g)); }

// ---------------------------------------------------------------------------
// Fused gate+up GEMM (fp16 single-pass) + SwiGLU epilogue -> fp16 h.
// CTA: M=128, N=128 (both matrices). Warp: 64 x 32 pair. 8 warps.
// ---------------------------------------------------------------------------
__global__ __launch_bounds__(THREADS, 1)
void k_gemm_gu(const __half* __restrict__ Ax,
               const __half* __restrict__ Bg,
               const __half* __restrict__ Bu,
               const float* __restrict__ gs, const float* __restrict__ us,
               __half* __restrict__ Hh, int K) {
    extern __shared__ __align__(128) int8_t sm[];
    const int tid = threadIdx.x, lane = tid & 31, wid = tid >> 5;
    const int wm = wid >> 2, wn = wid & 3;
    const size_t bm = (size_t)blockIdx.x * 128;
    const size_t bn = (size_t)blockIdx.y * 128;

    const __half* gA  = Ax + bm * K;
    const __half* gBg = Bg + bn * K;
    const __half* gBu = Bu + bn * K;

    float accg[4][4][4], accu[4][4][4];
    #pragma unroll
    for (int i = 0; i < 4; i++)
        #pragma unroll
        for (int j = 0; j < 4; j++)
            #pragma unroll
            for (int r = 0; r < 4; r++) { accg[i][j][r] = 0.f; accu[i][j][r] = 0.f; }

    auto load_stage = [&](int s, int k0) {
        int8_t* base = sm + s * STAGE2;
        #pragma unroll
        for (int i = 0; i < 4; i++) {
            int c = tid + i * THREADS, row = c >> 3, ch = c & 7;
            cp_async16(base + row * PITCH + ch * 16, gA + (size_t)row * K + k0 + ch * 8);
        }
        #pragma unroll
        for (int i = 0; i < 4; i++) {
            int c = tid + i * THREADS, row = c >> 3, ch = c & 7;
            cp_async16(base + MAT2 + row * PITCH + ch * 16,
                       gBg + (size_t)row * K + k0 + ch * 8);
        }
        #pragma unroll
        for (int i = 0; i < 4; i++) {
            int c = tid + i * THREADS, row = c >> 3, ch = c & 7;
            cp_async16(base + 2 * MAT2 + row * PITCH + ch * 16,
                       gBu + (size_t)row * K + k0 + ch * 8);
        }
        asm volatile("cp.async.commit_group;" ::: "memory");
    };

    const int KT = K / BK;
    load_stage(0, 0);
    load_stage(1, BK);

    const uint32_t smb = (uint32_t)__cvta_generic_to_shared(sm);
    const uint32_t a_off = (uint32_t)((lane & 15) * PITCH + (lane >> 4) * 16);
    const uint32_t b_off = (uint32_t)((lane & 7) * PITCH +
                                      ((lane >> 3) & 1) * 16 +
                                      (lane >> 4) * 8 * PITCH);

    int stage = 0;
    for (int kt = 0; kt < KT; kt++) {
        asm volatile("cp.async.wait_group 1;" ::: "memory");
        __syncthreads();
        if (kt + 2 < KT) {
            int s2 = stage + 2; if (s2 >= STAGES) s2 -= STAGES;
            load_stage(s2, (kt + 2) * BK);
        } else {
            asm volatile("cp.async.commit_group;" ::: "memory");
        }

        const uint32_t st  = smb + (uint32_t)(stage * STAGE2);
        const uint32_t sA  = st + (uint32_t)((wm * 64) * PITCH);
        const uint32_t sBg = st + (uint32_t)MAT2 + (uint32_t)((wn * 32) * PITCH);
        const uint32_t sBu = st + 2u * MAT2 + (uint32_t)((wn * 32) * PITCH);

        #pragma unroll
        for (int ks = 0; ks < 4; ks++) {
            const uint32_t kb = (uint32_t)(ks * 32);
            uint32_t bg[4][2], bu[4][2];
            #pragma unroll
            for (int np = 0; np < 2; np++) {
                uint32_t t4[4];
                ldm_x4(t4, sBg + (uint32_t)(np * 16 * PITCH) + b_off + kb);
                bg[2*np][0] = t4[0]; bg[2*np][1] = t4[1];
                bg[2*np+1][0] = t4[2]; bg[2*np+1][1] = t4[3];
                ldm_x4(t4, sBu + (uint32_t)(np * 16 * PITCH) + b_off + kb);
                bu[2*np][0] = t4[0]; bu[2*np][1] = t4[1];
                bu[2*np+1][0] = t4[2]; bu[2*np+1][1] = t4[3];
            }
            uint32_t af[4][4];
            #pragma unroll
            for (int mi = 0; mi < 4; mi++)
                ldm_x4(af[mi], sA + (uint32_t)(mi * 16 * PITCH) + a_off + kb);
            #pragma unroll
            for (int mi = 0; mi < 4; mi++)
                #pragma unroll
                for (int ni = 0; ni < 4; ni++) {
                    mma16816h(accg[mi][ni], af[mi], bg[ni]);
                    mma16816h(accu[mi][ni], af[mi], bu[ni]);
                }
        }
        if (++stage == STAGES) stage = 0;
    }

    // epilogue: hoisted scales -> SwiGLU -> fp16 h store
    const int r0b = (int)bm + wm * 64;
    const int c0b = (int)bn + wn * 32;
    float gsc0[4], gsc1[4], usc0[4], usc1[4];
    #pragma unroll
    for (int ni = 0; ni < 4; ni++) {
        const int c0 = c0b + ni * 8 + (lane & 3) * 2;
        gsc0[ni] = __ldg(gs + c0); gsc1[ni] = __ldg(gs + c0 + 1);
        usc0[ni] = __ldg(us + c0); usc1[ni] = __ldg(us + c0 + 1);
    }
    #pragma unroll
    for (int mi = 0; mi < 4; mi++) {
        const int r0 = r0b + mi * 16 + (lane >> 2);
        #pragma unroll
        for (int ni = 0; ni < 4; ni++) {
            const int c0 = c0b + ni * 8 + (lane & 3) * 2;
            float h00 = silu_f(accg[mi][ni][0] * gsc0[ni]) * (accu[mi][ni][0] * usc0[ni]);
            float h01 = silu_f(accg[mi][ni][1] * gsc1[ni]) * (accu[mi][ni][1] * usc1[ni]);
            float h10 = silu_f(accg[mi][ni][2] * gsc0[ni]) * (accu[mi][ni][2] * usc0[ni]);
            float h11 = silu_f(accg[mi][ni][3] * gsc1[ni]) * (accu[mi][ni][3] * usc1[ni]);
            *reinterpret_cast<__half2*>(Hh + (size_t)r0 * IDIM + c0) =
                __halves2half2(__float2half_rn(h00), __float2half_rn(h01));
            *reinterpret_cast<__half2*>(Hh + (size_t)(r0 + 8) * IDIM + c0) =
                __halves2half2(__float2half_rn(h10), __float2half_rn(h11));
        }
    }
}

// ---------------------------------------------------------------------------
// Down GEMM, fp16 single-pass, split-K=2 (R16, proven): partial C per z.
// ---------------------------------------------------------------------------
__global__ __launch_bounds__(THREADS, 1)
void k_gemm_sk(const __half* __restrict__ Ah,
               const __half* __restrict__ Bw,
               const float* __restrict__ scale,
               float* __restrict__ Cpart, int N, int Kld, int Kloc) {
    extern __shared__ __align__(128) int8_t sm[];
    const int tid = threadIdx.x, lane = tid & 31, wid = tid >> 5;
    const int wm = wid >> 2, wn = wid & 3;
    const size_t bm = (size_t)blockIdx.x * BM;
    const size_t bn = (size_t)blockIdx.y * BN;
    const int k0g = blockIdx.z * Kloc;

    const __half* gA = Ah + bm * Kld + k0g;
    const __half* gB = Bw + bn * Kld + k0g;
    float* C = Cpart + (size_t)blockIdx.z * MDIM * HDIM;

    float acc[4][8][4];
    #pragma unroll
    for (int i = 0; i < 4; i++)
        #pragma unroll
        for (int j = 0; j < 8; j++)
            #pragma unroll
            for (int r = 0; r < 4; r++) acc[i][j][r] = 0.0f;

    auto load_stage = [&](int s, int k0) {
        int8_t* base = sm + s * STAGE_B;
        #pragma unroll
        for (int i = 0; i < 4; i++) {
            int c = tid + i * THREADS, row = c >> 3, ch = c & 7;
            cp_async16(base + row * PITCH + ch * 16,
                       gA + (size_t)row * Kld + k0 + ch * 8);
        }
        #pragma unroll
        for (int i = 0; i < 8; i++) {
            int c = tid + i * THREADS, row = c >> 3, ch = c & 7;
            cp_async16(base + MAT_A + row * PITCH + ch * 16,
                       gB + (size_t)row * Kld + k0 + ch * 8);
        }
        asm volatile("cp.async.commit_group;" ::: "memory");
    };

    const int KT = Kloc / BK;
    load_stage(0, 0);
    load_stage(1, BK);

    const uint32_t smb = (uint32_t)__cvta_generic_to_shared(sm);
    const uint32_t a_off = (uint32_t)((lane & 15) * PITCH + (lane >> 4) * 16);
    const uint32_t b_off = (uint32_t)((lane & 7) * PITCH +
                                      ((lane >> 3) & 1) * 16 +
                                      (lane >> 4) * 8 * PITCH);

    int stage = 0;
    for (int kt = 0; kt < KT; kt++) {
        asm volatile("cp.async.wait_group 1;" ::: "memory");
        __syncthreads();
        if (kt + 2 < KT) {
            int s2 = stage + 2; if (s2 >= STAGES) s2 -= STAGES;
            load_stage(s2, (kt + 2) * BK);
        } else {
            asm volatile("cp.async.commit_group;" ::: "memory");
        }

        const uint32_t st  = smb + (uint32_t)(stage * STAGE_B);
        const uint32_t sA  = st + (uint32_t)((wm * 64) * PITCH);
        const uint32_t sB  = st + (uint32_t)MAT_A + (uint32_t)((wn * 64) * PITCH);

        #pragma unroll
        for (int ks = 0; ks < 4; ks++) {
            const uint32_t kb = (uint32_t)(ks * 32);
            uint32_t bf[8][2];
            #pragma unroll
            for (int np = 0; np < 4; np++) {
                uint32_t t4[4];
                ldm_x4(t4, sB + (uint32_t)(np * 16 * PITCH) + b_off + kb);
                bf[2 * np][0] = t4[0]; bf[2 * np][1] = t4[1];
                bf[2 * np + 1][0] = t4[2]; bf[2 * np + 1][1] = t4[3];
            }
            uint32_t af[4][4];
            #pragma unroll
            for (int mi = 0; mi < 4; mi++)
                ldm_x4(af[mi], sA + (uint32_t)(mi * 16 * PITCH) + a_off + kb);
            #pragma unroll
            for (int mi = 0; mi < 4; mi++)
                #pragma unroll
                for (int ni = 0; ni < 8; ni++)
                    mma16816h(acc[mi][ni], af[mi], bf[ni]);
        }
        if (++stage == STAGES) stage = 0;
    }

    const int r0b = (int)bm + wm * 64;
    const int c0b = (int)bn + wn * 64;
    #pragma unroll
    for (int mi = 0; mi < 4; mi++) {
        const int r0 = r0b + mi * 16 + (lane >> 2);
        #pragma unroll
        for (int ni = 0; ni < 8; ni++) {
            const int c0 = c0b + ni * 8 + (lane & 3) * 2;
            const float s0 = __ldg(scale + c0), s1 = __ldg(scale + c0 + 1);
            float2 v0 = make_float2(acc[mi][ni][0] * s0, acc[mi][ni][1] * s1);
            float2 v1 = make_float2(acc[mi][ni][2] * s0, acc[mi][ni][3] * s1);
            *reinterpret_cast<float2*>(C + (size_t)r0 * N + c0) = v0;
            *reinterpret_cast<float2*>(C + (size_t)(r0 + 8) * N + c0) = v1;
        }
    }
}

// combine the two split-K partials
__global__ void k_add(const float4* __restrict__ p0, const float4* __restrict__ p1,
                      float4* __restrict__ out, int n4) {
    int i = blockIdx.x * blockDim.x + threadIdx.x;
    int stride = gridDim.x * blockDim.x;
    for (; i < n4; i += stride) {
        float4 a = p0[i], b = p1[i];
        out[i] = make_float4(a.x + b.x, a.y + b.y, a.z + b.z, a.w + b.w);
    }
}

// ---------------------------------------------------------------------------
// Merged prep: all three weights -> fp16 (exact), x -> fp16 single.
// blockIdx.x >> 12 selects the job (4096 blocks each).
// ---------------------------------------------------------------------------
__global__ __launch_bounds__(256)
void k_prep(const int4* __restrict__ gwq, const int4* __restrict__ uwq,
            const int4* __restrict__ dwq, const float4* __restrict__ x,
            uint2* __restrict__ wg, uint2* __restrict__ wu,
            uint2* __restrict__ wd, uint2* __restrict__ xh) {
    const int job = blockIdx.x >> 12;
    const int blk = blockIdx.x & 4095;
    const int stride = 4096 * 256;
    int i = blk * 256 + threadIdx.x;

    if (job < 3) {
        const int4* src = (job == 0) ? gwq : (job == 1) ? uwq : dwq;
        uint2* dst = (job == 0) ? wg : (job == 1) ? wu : wd;
        const int n4 = IDIM * HDIM / 4;
        for (; i < n4; i += stride) {
            int4 v = src[i];
            __half2 a0 = __halves2half2(__float2half_rn((float)v.x),
                                        __float2half_rn((float)v.y));
            __half2 a1 = __halves2half2(__float2half_rn((float)v.z),
                                        __float2half_rn((float)v.w));
            dst[i] = make_uint2(*reinterpret_cast<uint32_t*>(&a0),
                                *reinterpret_cast<uint32_t*>(&a1));
        }
    } else {
        const int n4 = MDIM * HDIM / 4;
        for (; i < n4; i += stride) {
            float4 v = x[i];
            __half2 a0 = __halves2half2(__float2half_rn(v.x), __float2half_rn(v.y));
            __half2 a1 = __halves2half2(__float2half_rn(v.z), __float2half_rn(v.w));
            xh[i] = make_uint2(*reinterpret_cast<uint32_t*>(&a0),
                               *reinterpret_cast<uint32_t*>(&a1));
        }
    }
}

// ---------------------------------------------------------------------------
// Launch
// ---------------------------------------------------------------------------
extern "C" void kernel_launch(void* const* d_in, const int* in_sizes, int n_in,
                              void* d_out, int out_size) {
    const float* x   = (const float*)d_in[0];
    const int*   gwq = (const int*)  d_in[1];
    const float* gsc = (const float*)d_in[2];
    const int*   uwq = (const int*)  d_in[3];
    const float* usc = (const float*)d_in[4];
    const int*   dwq = (const int*)  d_in[5];
    const float* dsc = (const float*)d_in[6];
    float* out = (float*)d_out;

    cudaFuncSetAttribute(k_gemm_sk, cudaFuncAttributeMaxDynamicSharedMemorySize, SMEM_B);
    cudaFuncSetAttribute(k_gemm_gu, cudaFuncAttributeMaxDynamicSharedMemorySize, SMEM2);

    __half *wg, *wu, *wd, *xh, *hh;
    float *part;
    cudaGetSymbolAddress((void**)&wg, g_wg);
    cudaGetSymbolAddress((void**)&wu, g_wu);
    cudaGetSymbolAddress((void**)&wd, g_wd);
    cudaGetSymbolAddress((void**)&xh, g_xh);
    cudaGetSymbolAddress((void**)&hh, g_hh);
    cudaGetSymbolAddress((void**)&part, g_part);

    k_prep<<<4 * 4096, 256>>>((const int4*)gwq, (const int4*)uwq,
                              (const int4*)dwq, (const float4*)x,
                              (uint2*)wg, (uint2*)wu, (uint2*)wd, (uint2*)xh);

    dim3 grid1(MDIM / 128, IDIM / 128);   // (32, 112), m fastest for W-slab L2 reuse
    k_gemm_gu<<<grid1, THREADS, SMEM2>>>(xh, wg, wu, gsc, usc, hh, HDIM);

    dim3 grid2(MDIM / BM, HDIM / BN, 2);  // (32, 16, 2) split-K
    k_gemm_sk<<<grid2, THREADS, SMEM_B>>>(hh, wd, dsc, part, HDIM, IDIM, IDIM / 2);

    k_add<<<2048, 256>>>((const float4*)part,
                         (const float4*)(part + (size_t)MDIM * HDIM),
                         (float4*)out, MDIM * HDIM / 4);
}